// round 6
// baseline (speedup 1.0000x reference)
#include <cuda_runtime.h>
#include <cuda_fp16.h>

#define BATCH 128
#define DIN   512
#define HID   1024
#define G4    4096
#define STEPS 64
#define TOFF  55   // (128 - 64 - 9)

typedef unsigned int u32;

// ---------------- device scratch (no allocations allowed) -----------------
__device__ float  g_xproj[(size_t)STEPS * BATCH * G4];
__device__ __half g_h0hi[2][BATCH * HID], g_h0lo[2][BATCH * HID];
__device__ __half g_h1hi[2][BATCH * HID], g_h1lo[2][BATCH * HID];
__device__ float  g_c0[BATCH * HID];
__device__ uint4  g_whh0p[(size_t)512 * 64 * 32];
__device__ uint4  g_wih1p[(size_t)512 * 64 * 32];
__device__ uint4  g_whh1p[(size_t)512 * 64 * 32];
__device__ uint4  g_wih0p[(size_t)512 * 32 * 32];
__device__ u32    g_bar_count, g_bar_gen;

__device__ __forceinline__ float sigm(float x) { return 1.0f / (1.0f + expf(-x)); }
__device__ __forceinline__ u32 h2u(__half2 h) { return *(u32*)&h; }

__device__ __forceinline__ void mma_f16(float* d, const u32* a, const u32* b) {
    asm volatile("mma.sync.aligned.m16n8k16.row.col.f32.f16.f16.f32 "
        "{%0,%1,%2,%3},{%4,%5,%6,%7},{%8,%9},{%0,%1,%2,%3};"
        : "+f"(d[0]), "+f"(d[1]), "+f"(d[2]), "+f"(d[3])
        : "r"(a[0]), "r"(a[1]), "r"(a[2]), "r"(a[3]), "r"(b[0]), "r"(b[1]));
}
__device__ __forceinline__ u32 smem_u32(const void* p) {
    u32 a;
    asm("{ .reg .u64 t; cvta.to.shared.u64 t, %1; cvt.u32.u64 %0, t; }" : "=r"(a) : "l"(p));
    return a;
}
__device__ __forceinline__ void cpa16(u32 dst, const void* src) {
    asm volatile("cp.async.cg.shared.global [%0], [%1], 16;"
                 :: "r"(dst), "l"(__cvta_generic_to_global(src)) : "memory");
}
__device__ __forceinline__ void cpa_commit() {
    asm volatile("cp.async.commit_group;" ::: "memory");
}
template<int N> __device__ __forceinline__ void cpa_wait() {
    asm volatile("cp.async.wait_group %0;" :: "n"(N) : "memory");
}
__device__ __forceinline__ void ldm4(u32* r, u32 addr) {
    asm volatile("ldmatrix.sync.aligned.m8n8.x4.shared.b16 {%0,%1,%2,%3}, [%4];"
        : "=r"(r[0]), "=r"(r[1]), "=r"(r[2]), "=r"(r[3]) : "r"(addr));
}

// persistent-kernel smem: 4 stages
//  AHI: s*10240   ALO: 40960 + s*10240   B: 81920 + s*8192
#define PS_ALO   40960
#define PS_B     81920
#define PS_TOTAL 114688

// ---------------- grid-wide software barrier -------------------------------
// gen-th call (gen starts at 0); 128 CTAs.
__device__ __forceinline__ void grid_barrier(int gen) {
    __syncthreads();
    if (threadIdx.x == 0) {
        __threadfence();
        u32 prev = atomicAdd(&g_bar_count, 1u);
        if (prev == (u32)(gen * 128 + 127)) {
            atomicExch(&g_bar_gen, (u32)(gen + 1));
        } else {
            u32 g;
            do {
                __nanosleep(64);
                asm volatile("ld.acquire.gpu.u32 %0, [%1];"
                             : "=r"(g) : "l"((const u32*)&g_bar_gen));
            } while (g <= (u32)gen);
        }
    }
    __syncthreads();
}

// ---------------- init states ----------------------------------------------
__global__ void init_states() {
    int i = blockIdx.x * blockDim.x + threadIdx.x;
    if (i == 0) { g_bar_count = 0u; g_bar_gen = 0u; }
    if (i < BATCH * HID) {
        __half z = __float2half(0.f);
        g_h0hi[0][i] = z; g_h0lo[0][i] = z; g_h0hi[1][i] = z; g_h0lo[1][i] = z;
        g_h1hi[0][i] = z; g_h1lo[0][i] = z; g_h1hi[1][i] = z; g_h1lo[1][i] = z;
        g_c0[i] = 0.f;
    }
}

// ---------------- weight packer (single launch) ----------------------------
__device__ __forceinline__ void pack_one(
    const float* __restrict__ W, uint4* __restrict__ dst, int Kt, int idx)
{
    int lane = idx & 31;
    int rest = idx >> 5;
    int kt = rest % Kt, nt = rest / Kt;
    int K = Kt * 16;
    int n = nt * 8 + (lane >> 2);
    int k0 = kt * 16 + (lane & 3) * 2;
    const float* wr = W + (size_t)n * K + k0;
    float w00 = wr[0], w01 = wr[1], w10 = wr[8], w11 = wr[9];
    __half h00 = __float2half_rn(w00), h01 = __float2half_rn(w01);
    __half h10 = __float2half_rn(w10), h11 = __float2half_rn(w11);
    uint4 v;
    v.x = h2u(__halves2half2(h00, h01));
    v.y = h2u(__halves2half2(h10, h11));
    v.z = h2u(__halves2half2(__float2half_rn(w00 - __half2float(h00)),
                             __float2half_rn(w01 - __half2float(h01))));
    v.w = h2u(__halves2half2(__float2half_rn(w10 - __half2float(h10)),
                             __float2half_rn(w11 - __half2float(h11))));
    dst[idx] = v;
}
#define PACK_N64 (512 * 64 * 32)
#define PACK_N32 (512 * 32 * 32)
__global__ void pack_all(const float* __restrict__ Whh0, const float* __restrict__ Wih1,
                         const float* __restrict__ Whh1, const float* __restrict__ Wih0) {
    int idx = blockIdx.x * 256 + threadIdx.x;
    if (idx < PACK_N64)               pack_one(Whh0, g_whh0p, 64, idx);
    else if (idx < 2 * PACK_N64)      pack_one(Wih1, g_wih1p, 64, idx - PACK_N64);
    else if (idx < 3 * PACK_N64)      pack_one(Whh1, g_whh1p, 64, idx - 2 * PACK_N64);
    else                              pack_one(Wih0, g_wih0p, 32, idx - 3 * PACK_N64);
}

// ===========================================================================
// Persistent step kernel (all 64 steps + L0(0) prologue).
// Grid 128, 256 threads = 8 warps: wg = w&3 (mtiles 2wg,2wg+1), ng = w>>2.
// Phase A (kt<32, A=h0(t+1)): ng0 -> L1 (wih1), ng1 -> L0 (whh0), both subs.
// Phase B (kt>=32, A=h1(t)):  L1 (whh1) split by k-sub: ng0 sub0 -> acc,
//                             ng1 sub1 -> accB; reduced via smem per step.
// ===========================================================================
__global__ void __launch_bounds__(256) step_persist(
    const float* __restrict__ bih1, const float* __restrict__ bhh1)
{
    extern __shared__ char smem[];
    const int tid = threadIdx.x, bx = blockIdx.x;
    const int w = tid >> 5, lane = tid & 31, qr = lane >> 2, qc = lane & 3;
    const int wg = w & 3, ng = w >> 2;
    const u32 sb = smem_u32(smem);
    const int n0 = bx * 8 + qc * 2;

    // ---- prologue: L0 step 0 (h0 = 0) on this CTA's 8 columns ----
    for (int i = tid; i < 128 * 8; i += 256) {
        int m = i >> 3, u = i & 7;
        int n = bx * 8 + u;
        const float* xr = g_xproj + (size_t)m * G4;
        float iv = xr[n], gv = xr[2048 + n], ov = xr[3072 + n];
        float cn = sigm(iv) * tanhf(gv);
        g_c0[m * HID + n] = cn;
        float h = sigm(ov) * tanhf(cn);
        __half hh = __float2half_rn(h);
        g_h0hi[1][m * HID + n] = hh;
        g_h0lo[1][m * HID + n] = __float2half_rn(h - __half2float(hh));
    }
    grid_barrier(0);

    // biases (L1) in regs
    float bs[4][2];
#pragma unroll
    for (int g = 0; g < 4; g++) {
        bs[g][0] = bih1[g * 1024 + n0] + bhh1[g * 1024 + n0];
        bs[g][1] = bih1[g * 1024 + n0 + 1] + bhh1[g * 1024 + n0 + 1];
    }
    // c-state in regs: ng0 holds c1 (zeros), ng1 holds c0 (from prologue)
    float cr[2][4];
#pragma unroll
    for (int mt = 0; mt < 2; mt++)
#pragma unroll
        for (int r = 0; r < 4; r++) cr[mt][r] = 0.f;
    if (ng == 1) {
#pragma unroll
        for (int mt = 0; mt < 2; mt++)
#pragma unroll
            for (int rr = 0; rr < 2; rr++) {
                int m = (wg * 2 + mt) * 16 + qr + rr * 8;
                cr[mt][rr * 2 + 0] = g_c0[m * HID + n0];
                cr[mt][rr * 2 + 1] = g_c0[m * HID + n0 + 1];
            }
    }

    // invariant staging coords (A: thread stages one half-row; B: 2 uint4)
    const int rowA = tid >> 1;
    const int cA   = (tid & 1) * 2;
    const size_t gAo = (size_t)rowA * HID + cA * 8;
    const u32  dA    = sb + rowA * 80 + cA * 16;
    const int ntB = tid >> 6, jB = (tid >> 5) & 1, lnB = tid & 31;
    const size_t bBase = ((size_t)(ntB * 128 + bx) * 64 + jB) * 32 + lnB;
    const u32  dB    = sb + PS_B + (((ntB * 2 + jB) * 32 + lnB) << 4);
    // A-fragment bases for the warp's two mtiles
    u32 aF[2];
#pragma unroll
    for (int mt = 0; mt < 2; mt++)
        aF[mt] = sb + ((wg * 2 + mt) * 16 + (lane & 15)) * 80 + ((lane >> 4) * 16);

    float* red = (float*)smem;   // 16KB reduction buffer (reuses A stage 0)

#pragma unroll 1
    for (int t = 0; t < STEPS; t++) {
        const int do_l0 = (t < STEPS - 1);
        const __half* AhA = g_h0hi[(t + 1) & 1];
        const __half* AlA = g_h0lo[(t + 1) & 1];
        const __half* AhB = g_h1hi[t & 1];
        const __half* AlB = g_h1lo[t & 1];

        float acc[2][4][4], accB[2][4][4];
#pragma unroll
        for (int i = 0; i < 2; i++)
#pragma unroll
            for (int j = 0; j < 4; j++)
#pragma unroll
                for (int k = 0; k < 4; k++) { acc[i][j][k] = 0.f; accB[i][j][k] = 0.f; }

        auto issue = [&](int kt) {
            int s = kt & 3;
            bool pa = kt < 32;
            int kk = pa ? kt : kt - 32;
            const __half* Ah = pa ? AhA : AhB;
            const __half* Al = pa ? AlA : AlB;
            size_t ga = gAo + kk * 32;
            u32 da = dA + s * 10240;
            cpa16(da,               Ah + ga);
            cpa16(da + 16,          Ah + ga + 8);
            cpa16(da + PS_ALO,      Al + ga);
            cpa16(da + PS_ALO + 16, Al + ga + 8);
            size_t bsrc = bBase + (size_t)kk * 64;
            u32 db = dB + s * 8192;
            if (pa) {
                cpa16(db, g_wih1p + bsrc);
                if (do_l0) cpa16(db + 4096, g_whh0p + bsrc);
            } else {
                cpa16(db, g_whh1p + bsrc);
            }
        };

        issue(0); cpa_commit();
        issue(1); cpa_commit();
        issue(2); cpa_commit();

#pragma unroll 1
        for (int kt = 0; kt < 64; kt++) {
            int s = kt & 3;
            cpa_wait<2>();
            __syncthreads();
            if (kt + 3 < 64) issue(kt + 3);
            cpa_commit();
            const uint4* bst = (const uint4*)(smem + PS_B + s * 8192);
            const u32 aBase0 = aF[0] + s * 10240;
            const u32 aBase1 = aF[1] + s * 10240;
            if (kt < 32) {
                // phase A: ng selects matrix (0: wih1->L1, 1: whh0->L0)
                if (ng == 0 || do_l0) {
#pragma unroll
                    for (int sub = 0; sub < 2; sub++) {
                        u32 ah[2][4], al[2][4];
                        ldm4(ah[0], aBase0 + sub * 32);
                        ldm4(al[0], aBase0 + PS_ALO + sub * 32);
                        ldm4(ah[1], aBase1 + sub * 32);
                        ldm4(al[1], aBase1 + PS_ALO + sub * 32);
#pragma unroll
                        for (int nt = 0; nt < 4; nt++) {
                            uint4 bp = bst[ng * 256 + (nt * 2 + sub) * 32 + lane];
                            u32 bh[2] = {bp.x, bp.y}, bl[2] = {bp.z, bp.w};
#pragma unroll
                            for (int mt = 0; mt < 2; mt++) {
                                mma_f16(acc[mt][nt], ah[mt], bh);
                                mma_f16(acc[mt][nt], al[mt], bh);
                                mma_f16(acc[mt][nt], ah[mt], bl);
                            }
                        }
                    }
                }
            } else {
                // phase B: L1 (whh1) split by sub = ng
                const int sub = ng;
                u32 ah[2][4], al[2][4];
                ldm4(ah[0], aBase0 + sub * 32);
                ldm4(al[0], aBase0 + PS_ALO + sub * 32);
                ldm4(ah[1], aBase1 + sub * 32);
                ldm4(al[1], aBase1 + PS_ALO + sub * 32);
#pragma unroll
                for (int nt = 0; nt < 4; nt++) {
                    uint4 bp = bst[(nt * 2 + sub) * 32 + lane];
                    u32 bh[2] = {bp.x, bp.y}, bl[2] = {bp.z, bp.w};
#pragma unroll
                    for (int mt = 0; mt < 2; mt++) {
                        float* d = (ng == 0) ? acc[mt][nt] : accB[mt][nt];
                        mma_f16(d, ah[mt], bh);
                        mma_f16(d, al[mt], bh);
                        mma_f16(d, ah[mt], bl);
                    }
                }
            }
        }
        cpa_wait<0>();
        __syncthreads();

        // ---- reduce ng1's phase-B L1 partials into ng0's acc ----
        if (ng == 1) {
#pragma unroll
            for (int mt = 0; mt < 2; mt++)
#pragma unroll
                for (int nt = 0; nt < 4; nt++)
#pragma unroll
                    for (int r = 0; r < 4; r++)
                        red[((((wg * 2 + mt) * 4 + nt) * 4 + r) << 5) + lane] = accB[mt][nt][r];
        }
        __syncthreads();

        if (ng == 0) {
            // ---- L1(t) epilogue ----
            __half* Hhi = g_h1hi[(t + 1) & 1];
            __half* Hlo = g_h1lo[(t + 1) & 1];
#pragma unroll
            for (int mt = 0; mt < 2; mt++) {
#pragma unroll
                for (int rr = 0; rr < 2; rr++) {
                    int m = (wg * 2 + mt) * 16 + qr + rr * 8;
                    __half hh[2], hl[2];
#pragma unroll
                    for (int e = 0; e < 2; e++) {
                        int ri = rr * 2 + e;
                        float pI = red[((((wg * 2 + mt) * 4 + 0) * 4 + ri) << 5) + lane];
                        float pF = red[((((wg * 2 + mt) * 4 + 1) * 4 + ri) << 5) + lane];
                        float pG = red[((((wg * 2 + mt) * 4 + 2) * 4 + ri) << 5) + lane];
                        float pO = red[((((wg * 2 + mt) * 4 + 3) * 4 + ri) << 5) + lane];
                        float iv = acc[mt][0][ri] + pI + bs[0][e];
                        float fv = acc[mt][1][ri] + pF + bs[1][e];
                        float gv = acc[mt][2][ri] + pG + bs[2][e];
                        float ov = acc[mt][3][ri] + pO + bs[3][e];
                        float cn = sigm(fv) * cr[mt][ri] + sigm(iv) * tanhf(gv);
                        cr[mt][ri] = cn;
                        float h = sigm(ov) * tanhf(cn);
                        hh[e] = __float2half_rn(h);
                        hl[e] = __float2half_rn(h - __half2float(hh[e]));
                    }
                    *(__half2*)&Hhi[m * HID + n0] = __halves2half2(hh[0], hh[1]);
                    *(__half2*)&Hlo[m * HID + n0] = __halves2half2(hl[0], hl[1]);
                }
            }
        } else if (do_l0) {
            // ---- L0(t+1) epilogue ----
            const float* xp = g_xproj + (size_t)(t + 1) * BATCH * G4;
            __half* Hhi = g_h0hi[t & 1];
            __half* Hlo = g_h0lo[t & 1];
#pragma unroll
            for (int mt = 0; mt < 2; mt++) {
#pragma unroll
                for (int rr = 0; rr < 2; rr++) {
                    int m = (wg * 2 + mt) * 16 + qr + rr * 8;
                    const float* xr = xp + (size_t)m * G4 + n0;
                    float2 xi = *(const float2*)(xr);
                    float2 xf = *(const float2*)(xr + 1024);
                    float2 xg = *(const float2*)(xr + 2048);
                    float2 xo = *(const float2*)(xr + 3072);
                    __half hh[2], hl[2];
#pragma unroll
                    for (int e = 0; e < 2; e++) {
                        int ri = rr * 2 + e;
                        float iv = acc[mt][0][ri] + (e ? xi.y : xi.x);
                        float fv = acc[mt][1][ri] + (e ? xf.y : xf.x);
                        float gv = acc[mt][2][ri] + (e ? xg.y : xg.x);
                        float ov = acc[mt][3][ri] + (e ? xo.y : xo.x);
                        float cn = sigm(fv) * cr[mt][ri] + sigm(iv) * tanhf(gv);
                        cr[mt][ri] = cn;
                        float h = sigm(ov) * tanhf(cn);
                        hh[e] = __float2half_rn(h);
                        hl[e] = __float2half_rn(h - __half2float(hh[e]));
                    }
                    *(__half2*)&Hhi[m * HID + n0] = __halves2half2(hh[0], hh[1]);
                    *(__half2*)&Hlo[m * HID + n0] = __halves2half2(hl[0], hl[1]);
                }
            }
        }
        grid_barrier(t + 1);
    }
}

// ===========================================================================
// xproj (round-5 validated, unchanged)
// ===========================================================================
__global__ void __launch_bounds__(256) xproj_kernel(
    const float* __restrict__ xs,
    const float* __restrict__ bih0, const float* __restrict__ bhh0)
{
    __shared__ __align__(16) __half sAhi[2][128][24];
    __shared__ __align__(16) __half sAlo[2][128][24];
    __shared__ uint4 sB[2][8][32];
    const int tid = threadIdx.x;
    const int nbx = blockIdx.x;
    const int mb  = blockIdx.y;
    const int w = tid >> 5, lane = tid & 31, qr = lane >> 2, qc = lane & 3;

    float acc[8][4];
#pragma unroll
    for (int j = 0; j < 8; j++)
#pragma unroll
        for (int k = 0; k < 4; k++) acc[j][k] = 0.f;

    const int srow = tid >> 1, sseg = tid & 1;
    const float* arow = xs + (size_t)(srow * 128 + TOFF + mb) * DIN + sseg * 8;

    float4 rf0, rf1;
    uint4 rb;
    auto ld = [&](int kt) {
        rf0 = *(const float4*)(arow + kt * 16);
        rf1 = *(const float4*)(arow + kt * 16 + 4);
        rb = g_wih0p[((size_t)(nbx * 8 + w) * 32 + kt) * 32 + lane];
    };
    ld(0);
#pragma unroll 1
    for (int kt = 0; kt < 32; kt++) {
        int s = kt & 1;
        __half2* dh = (__half2*)&sAhi[s][srow][sseg * 8];
        __half2* dl = (__half2*)&sAlo[s][srow][sseg * 8];
        float v[8] = {rf0.x, rf0.y, rf0.z, rf0.w, rf1.x, rf1.y, rf1.z, rf1.w};
#pragma unroll
        for (int p = 0; p < 4; p++) {
            float x0 = v[p * 2], x1 = v[p * 2 + 1];
            __half a0 = __float2half_rn(x0), a1 = __float2half_rn(x1);
            dh[p] = __halves2half2(a0, a1);
            dl[p] = __halves2half2(__float2half_rn(x0 - __half2float(a0)),
                                   __float2half_rn(x1 - __half2float(a1)));
        }
        sB[s][w][lane] = rb;
        __syncthreads();
        if (kt + 1 < 32) ld(kt + 1);
        {
            const int r = w * 16 + qr;
            u32 ah[4], al[4];
            ah[0] = *(const u32*)&sAhi[s][r][qc * 2];
            ah[1] = *(const u32*)&sAhi[s][r + 8][qc * 2];
            ah[2] = *(const u32*)&sAhi[s][r][qc * 2 + 8];
            ah[3] = *(const u32*)&sAhi[s][r + 8][qc * 2 + 8];
            al[0] = *(const u32*)&sAlo[s][r][qc * 2];
            al[1] = *(const u32*)&sAlo[s][r + 8][qc * 2];
            al[2] = *(const u32*)&sAlo[s][r][qc * 2 + 8];
            al[3] = *(const u32*)&sAlo[s][r + 8][qc * 2 + 8];
#pragma unroll
            for (int nt = 0; nt < 8; nt++) {
                uint4 bp = sB[s][nt][lane];
                u32 bh[2] = {bp.x, bp.y}, bl[2] = {bp.z, bp.w};
                mma_f16(acc[nt], ah, bh);
                mma_f16(acc[nt], al, bh);
                mma_f16(acc[nt], ah, bl);
            }
        }
        __syncthreads();
    }

    const int m0g = mb * 128 + w * 16 + qr;
#pragma unroll
    for (int nt = 0; nt < 8; nt++) {
        int colb = nbx * 64 + nt * 8 + qc * 2;
        float bv0 = bih0[colb] + bhh0[colb];
        float bv1 = bih0[colb + 1] + bhh0[colb + 1];
        *(float2*)&g_xproj[(size_t)m0g * G4 + colb] =
            make_float2(acc[nt][0] + bv0, acc[nt][1] + bv1);
        *(float2*)&g_xproj[(size_t)(m0g + 8) * G4 + colb] =
            make_float2(acc[nt][2] + bv0, acc[nt][3] + bv1);
    }
}

// ---------------- classifier (unchanged) ------------------------------------
__global__ void __launch_bounds__(256) classifier_kernel(
    const float* __restrict__ Wcls, const float* __restrict__ bcls,
    const float* __restrict__ dropu, float* __restrict__ out)
{
    int gw = (blockIdx.x * blockDim.x + threadIdx.x) >> 5;
    int lane = threadIdx.x & 31;
    int j = gw >> 5;
    int b0 = (gw & 31) * 4;
    const __half* hi = g_h1hi[0];
    const __half* lo = g_h1lo[0];

    float acc[4] = {0.f, 0.f, 0.f, 0.f};
#pragma unroll
    for (int it = 0; it < 8; ++it) {
        int h = it * 128 + lane * 4;
        float4 wv = *(const float4*)&Wcls[(size_t)j * HID + h];
#pragma unroll
        for (int bi = 0; bi < 4; ++bi) {
            int b = b0 + bi;
            int idx = b * HID + h;
            __half2 a0 = *(const __half2*)&hi[idx];
            __half2 a1 = *(const __half2*)&hi[idx + 2];
            __half2 c0 = *(const __half2*)&lo[idx];
            __half2 c1 = *(const __half2*)&lo[idx + 2];
            float2 f0 = __half22float2(a0), f1 = __half22float2(a1);
            float2 g0 = __half22float2(c0), g1 = __half22float2(c1);
            float x0 = f0.x + g0.x, x1 = f0.y + g0.y;
            float x2 = f1.x + g1.x, x3 = f1.y + g1.y;
            float4 u = *(const float4*)&dropu[(size_t)b * HID + h];
            acc[bi] += (u.x > 0.5f ? x0 : 0.f) * wv.x
                     + (u.y > 0.5f ? x1 : 0.f) * wv.y
                     + (u.z > 0.5f ? x2 : 0.f) * wv.z
                     + (u.w > 0.5f ? x3 : 0.f) * wv.w;
        }
    }
#pragma unroll
    for (int bi = 0; bi < 4; ++bi) {
        float v = acc[bi];
#pragma unroll
        for (int off = 16; off; off >>= 1)
            v += __shfl_xor_sync(0xffffffffu, v, off);
        if (lane == 0)
            out[(size_t)(b0 + bi) * 1000 + j] = 2.0f * v + bcls[j];
    }
}

// ---------------- launch ----------------------------------------------------
extern "C" void kernel_launch(void* const* d_in, const int* in_sizes, int n_in,
                              void* d_out, int out_size)
{
    const float* xs    = (const float*)d_in[0];
    const float* Wih0  = (const float*)d_in[1];
    const float* Whh0  = (const float*)d_in[2];
    const float* bih0  = (const float*)d_in[3];
    const float* bhh0  = (const float*)d_in[4];
    const float* Wih1  = (const float*)d_in[5];
    const float* Whh1  = (const float*)d_in[6];
    const float* bih1  = (const float*)d_in[7];
    const float* bhh1  = (const float*)d_in[8];
    const float* Wcls  = (const float*)d_in[9];
    const float* bcls  = (const float*)d_in[10];
    const float* dropu = (const float*)d_in[11];
    float* out = (float*)d_out;

    cudaFuncSetAttribute(step_persist, cudaFuncAttributeMaxDynamicSharedMemorySize, PS_TOTAL);

    // 5 launches total; step_persist positioned to land under ncu -s 5 -c 1
    init_states<<<(BATCH * HID + 255) / 256, 256>>>();
    pack_all<<<(3 * PACK_N64 + PACK_N32) / 256, 256>>>(Whh0, Wih1, Whh1, Wih0);
    xproj_kernel<<<dim3(64, 64), 256>>>(xs, bih0, bhh0);
    step_persist<<<128, 256, PS_TOTAL>>>(bih1, bhh1);
    classifier_kernel<<<4000, 256>>>(Wcls, bcls, dropu, out);
}

// round 7
// speedup vs baseline: 1.0452x; 1.0452x over previous
#include <cuda_runtime.h>
#include <cuda_fp16.h>

#define BATCH 128
#define DIN   512
#define HID   1024
#define G4    4096
#define STEPS 64
#define TOFF  55   // (128 - 64 - 9)

typedef unsigned int u32;

// ---------------- device scratch (no allocations allowed) -----------------
__device__ float  g_xproj[(size_t)STEPS * BATCH * G4];
__device__ __half g_h0hi[2][BATCH * HID], g_h0lo[2][BATCH * HID];
__device__ __half g_h1hi[2][BATCH * HID], g_h1lo[2][BATCH * HID];
__device__ float  g_c0[BATCH * HID];
__device__ uint4  g_whh0p[(size_t)512 * 64 * 32];
__device__ uint4  g_wih1p[(size_t)512 * 64 * 32];
__device__ uint4  g_whh1p[(size_t)512 * 64 * 32];
__device__ uint4  g_wih0p[(size_t)512 * 32 * 32];
__device__ u32    g_bar_count, g_bar_gen;

__device__ __forceinline__ float sigm(float x) { return 1.0f / (1.0f + expf(-x)); }
__device__ __forceinline__ u32 h2u(__half2 h) { return *(u32*)&h; }

__device__ __forceinline__ void mma_f16(float* d, const u32* a, const u32* b) {
    asm volatile("mma.sync.aligned.m16n8k16.row.col.f32.f16.f16.f32 "
        "{%0,%1,%2,%3},{%4,%5,%6,%7},{%8,%9},{%0,%1,%2,%3};"
        : "+f"(d[0]), "+f"(d[1]), "+f"(d[2]), "+f"(d[3])
        : "r"(a[0]), "r"(a[1]), "r"(a[2]), "r"(a[3]), "r"(b[0]), "r"(b[1]));
}
__device__ __forceinline__ u32 smem_u32(const void* p) {
    u32 a;
    asm("{ .reg .u64 t; cvta.to.shared.u64 t, %1; cvt.u32.u64 %0, t; }" : "=r"(a) : "l"(p));
    return a;
}
__device__ __forceinline__ void cpa16(u32 dst, const void* src) {
    asm volatile("cp.async.cg.shared.global [%0], [%1], 16;"
                 :: "r"(dst), "l"(__cvta_generic_to_global(src)) : "memory");
}
__device__ __forceinline__ void cpa_commit() {
    asm volatile("cp.async.commit_group;" ::: "memory");
}
template<int N> __device__ __forceinline__ void cpa_wait() {
    asm volatile("cp.async.wait_group %0;" :: "n"(N) : "memory");
}
__device__ __forceinline__ void ldm4(u32* r, u32 addr) {
    asm volatile("ldmatrix.sync.aligned.m8n8.x4.shared.b16 {%0,%1,%2,%3}, [%4];"
        : "=r"(r[0]), "=r"(r[1]), "=r"(r[2]), "=r"(r[3]) : "r"(addr));
}

// persistent-kernel smem: 4 stages
//  AHI: s*10240   ALO: 40960 + s*10240   B: 81920 + s*8192
#define PS_ALO   40960
#define PS_B     81920
#define PS_TOTAL 114688

// ---------------- grid-wide software barrier (128 CTAs) --------------------
__device__ __forceinline__ void grid_barrier(int gen) {
    __syncthreads();
    if (threadIdx.x == 0) {
        __threadfence();
        u32 prev = atomicAdd(&g_bar_count, 1u);
        if (prev == (u32)(gen * 128 + 127)) {
            atomicExch(&g_bar_gen, (u32)(gen + 1));
        } else {
            u32 g;
            do {
                __nanosleep(64);
                asm volatile("ld.acquire.gpu.u32 %0, [%1];"
                             : "=r"(g) : "l"((const u32*)&g_bar_gen));
            } while (g <= (u32)gen);
        }
    }
    __syncthreads();
}

// ---------------- init states ----------------------------------------------
__global__ void init_states() {
    int i = blockIdx.x * blockDim.x + threadIdx.x;
    if (i == 0) { g_bar_count = 0u; g_bar_gen = 0u; }
    if (i < BATCH * HID) {
        __half z = __float2half(0.f);
        g_h0hi[0][i] = z; g_h0lo[0][i] = z; g_h0hi[1][i] = z; g_h0lo[1][i] = z;
        g_h1hi[0][i] = z; g_h1lo[0][i] = z; g_h1hi[1][i] = z; g_h1lo[1][i] = z;
        g_c0[i] = 0.f;
    }
}

// ---------------- weight packer (single launch) ----------------------------
__device__ __forceinline__ void pack_one(
    const float* __restrict__ W, uint4* __restrict__ dst, int Kt, int idx)
{
    int lane = idx & 31;
    int rest = idx >> 5;
    int kt = rest % Kt, nt = rest / Kt;
    int K = Kt * 16;
    int n = nt * 8 + (lane >> 2);
    int k0 = kt * 16 + (lane & 3) * 2;
    const float* wr = W + (size_t)n * K + k0;
    float w00 = wr[0], w01 = wr[1], w10 = wr[8], w11 = wr[9];
    __half h00 = __float2half_rn(w00), h01 = __float2half_rn(w01);
    __half h10 = __float2half_rn(w10), h11 = __float2half_rn(w11);
    uint4 v;
    v.x = h2u(__halves2half2(h00, h01));
    v.y = h2u(__halves2half2(h10, h11));
    v.z = h2u(__halves2half2(__float2half_rn(w00 - __half2float(h00)),
                             __float2half_rn(w01 - __half2float(h01))));
    v.w = h2u(__halves2half2(__float2half_rn(w10 - __half2float(h10)),
                             __float2half_rn(w11 - __half2float(h11))));
    dst[idx] = v;
}
#define PACK_N64 (512 * 64 * 32)
#define PACK_N32 (512 * 32 * 32)
__global__ void pack_all(const float* __restrict__ Whh0, const float* __restrict__ Wih1,
                         const float* __restrict__ Whh1, const float* __restrict__ Wih0) {
    int idx = blockIdx.x * 256 + threadIdx.x;
    if (idx < PACK_N64)               pack_one(Whh0, g_whh0p, 64, idx);
    else if (idx < 2 * PACK_N64)      pack_one(Wih1, g_wih1p, 64, idx - PACK_N64);
    else if (idx < 3 * PACK_N64)      pack_one(Whh1, g_whh1p, 64, idx - 2 * PACK_N64);
    else                              pack_one(Wih0, g_wih0p, 32, idx - 3 * PACK_N64);
}

// ===========================================================================
// Persistent step kernel (all 64 steps + L0(0) prologue).
// Grid 128, 512 threads = 16 warps: wg = w&7 (mtile = rows wg*16..+15),
// ng = w>>3.
// Phase A (kt<32, A=h0(t+1)): ng0 -> L1 (wih1), ng1 -> L0 (whh0).
// Phase B (kt>=32, A=h1(t)):  L1 (whh1) split by k-sub = ng; ng1 partials
//                             reduced into ng0 via 16KB smem buffer per step.
// ===========================================================================
__global__ void __launch_bounds__(512) step_persist(
    const float* __restrict__ bih1, const float* __restrict__ bhh1)
{
    extern __shared__ char smem[];
    const int tid = threadIdx.x, bx = blockIdx.x;
    const int w = tid >> 5, lane = tid & 31, qr = lane >> 2, qc = lane & 3;
    const int wg = w & 7, ng = w >> 3;
    const u32 sb = smem_u32(smem);
    const int n0 = bx * 8 + qc * 2;

    // ---- prologue: L0 step 0 (h0 = 0) on this CTA's 8 columns ----
    for (int i = tid; i < 128 * 8; i += 512) {
        int m = i >> 3, u = i & 7;
        int n = bx * 8 + u;
        const float* xr = g_xproj + (size_t)m * G4;
        float iv = xr[n], gv = xr[2048 + n], ov = xr[3072 + n];
        float cn = sigm(iv) * tanhf(gv);
        g_c0[m * HID + n] = cn;
        float h = sigm(ov) * tanhf(cn);
        __half hh = __float2half_rn(h);
        g_h0hi[1][m * HID + n] = hh;
        g_h0lo[1][m * HID + n] = __float2half_rn(h - __half2float(hh));
    }
    grid_barrier(0);

    // biases (L1) in regs
    float bs[4][2];
#pragma unroll
    for (int g = 0; g < 4; g++) {
        bs[g][0] = bih1[g * 1024 + n0] + bhh1[g * 1024 + n0];
        bs[g][1] = bih1[g * 1024 + n0 + 1] + bhh1[g * 1024 + n0 + 1];
    }
    // c-state in regs: ng0 -> c1 (zeros), ng1 -> c0 (from prologue), mtile wg
    float cr[4] = {0.f, 0.f, 0.f, 0.f};
    if (ng == 1) {
#pragma unroll
        for (int rr = 0; rr < 2; rr++) {
            int m = wg * 16 + qr + rr * 8;
            cr[rr * 2 + 0] = g_c0[m * HID + n0];
            cr[rr * 2 + 1] = g_c0[m * HID + n0 + 1];
        }
    }

    // invariant staging coords: A: 4 threads/row, 16B each (hi + lo)
    const int rowA = tid >> 2;
    const int cA   = tid & 3;
    const size_t gAo = (size_t)rowA * HID + cA * 8;
    const u32  dA    = sb + rowA * 80 + cA * 16;
    // B staging: threads 0..255 only
    const int ntB = (tid >> 6) & 3, jB = (tid >> 5) & 1, lnB = tid & 31;
    const size_t bBase = ((size_t)(ntB * 128 + bx) * 64 + jB) * 32 + lnB;
    const u32  dB    = sb + PS_B + (((ntB * 2 + jB) * 32 + lnB) << 4);
    const bool doB = (tid < 256);
    // A-fragment base for this warp's mtile
    const u32 aF = sb + (wg * 16 + (lane & 15)) * 80 + ((lane >> 4) * 16);

    float* red = (float*)smem;   // 16KB reduction buffer (reuses A stage 0)

#pragma unroll 1
    for (int t = 0; t < STEPS; t++) {
        const int do_l0 = (t < STEPS - 1);
        const __half* AhA = g_h0hi[(t + 1) & 1];
        const __half* AlA = g_h0lo[(t + 1) & 1];
        const __half* AhB = g_h1hi[t & 1];
        const __half* AlB = g_h1lo[t & 1];

        float acc[4][4], accB[4][4];
#pragma unroll
        for (int j = 0; j < 4; j++)
#pragma unroll
            for (int k = 0; k < 4; k++) { acc[j][k] = 0.f; accB[j][k] = 0.f; }

        auto issue = [&](int kt) {
            int s = kt & 3;
            bool pa = kt < 32;
            int kk = pa ? kt : kt - 32;
            const __half* Ah = pa ? AhA : AhB;
            const __half* Al = pa ? AlA : AlB;
            size_t ga = gAo + kk * 32;
            u32 da = dA + s * 10240;
            cpa16(da,          Ah + ga);
            cpa16(da + PS_ALO, Al + ga);
            if (doB) {
                size_t bsrc = bBase + (size_t)kk * 64;
                u32 db = dB + s * 8192;
                if (pa) {
                    cpa16(db, g_wih1p + bsrc);
                    if (do_l0) cpa16(db + 4096, g_whh0p + bsrc);
                } else {
                    cpa16(db, g_whh1p + bsrc);
                }
            }
        };

        issue(0); cpa_commit();
        issue(1); cpa_commit();
        issue(2); cpa_commit();

#pragma unroll 1
        for (int kt = 0; kt < 64; kt++) {
            int s = kt & 3;
            cpa_wait<2>();
            __syncthreads();
            if (kt + 3 < 64) issue(kt + 3);
            cpa_commit();
            const uint4* bst = (const uint4*)(smem + PS_B + s * 8192);
            const u32 aBase = aF + s * 10240;
            if (kt < 32) {
                // phase A: ng selects matrix (0: wih1->L1, 1: whh0->L0)
                if (ng == 0 || do_l0) {
#pragma unroll
                    for (int sub = 0; sub < 2; sub++) {
                        u32 ah[4], al[4];
                        ldm4(ah, aBase + sub * 32);
                        ldm4(al, aBase + PS_ALO + sub * 32);
#pragma unroll
                        for (int nt = 0; nt < 4; nt++) {
                            uint4 bp = bst[ng * 256 + (nt * 2 + sub) * 32 + lane];
                            u32 bh[2] = {bp.x, bp.y}, bl[2] = {bp.z, bp.w};
                            mma_f16(acc[nt], ah, bh);
                            mma_f16(acc[nt], al, bh);
                            mma_f16(acc[nt], ah, bl);
                        }
                    }
                }
            } else {
                // phase B: L1 (whh1), k-sub = ng
                const int sub = ng;
                u32 ah[4], al[4];
                ldm4(ah, aBase + sub * 32);
                ldm4(al, aBase + PS_ALO + sub * 32);
#pragma unroll
                for (int nt = 0; nt < 4; nt++) {
                    uint4 bp = bst[(nt * 2 + sub) * 32 + lane];
                    u32 bh[2] = {bp.x, bp.y}, bl[2] = {bp.z, bp.w};
                    float* d = (ng == 0) ? acc[nt] : accB[nt];
                    mma_f16(d, ah, bh);
                    mma_f16(d, al, bh);
                    mma_f16(d, ah, bl);
                }
            }
        }
        cpa_wait<0>();
        __syncthreads();

        // ---- reduce ng1's phase-B L1 partials into ng0's acc ----
        if (ng == 1) {
#pragma unroll
            for (int nt = 0; nt < 4; nt++)
#pragma unroll
                for (int r = 0; r < 4; r++)
                    red[(((wg * 4 + nt) * 4 + r) << 5) + lane] = accB[nt][r];
        }
        __syncthreads();

        if (ng == 0) {
            // ---- L1(t) epilogue ----
            __half* Hhi = g_h1hi[(t + 1) & 1];
            __half* Hlo = g_h1lo[(t + 1) & 1];
#pragma unroll
            for (int rr = 0; rr < 2; rr++) {
                int m = wg * 16 + qr + rr * 8;
                __half hh[2], hl[2];
#pragma unroll
                for (int e = 0; e < 2; e++) {
                    int ri = rr * 2 + e;
                    float pI = red[(((wg * 4 + 0) * 4 + ri) << 5) + lane];
                    float pF = red[(((wg * 4 + 1) * 4 + ri) << 5) + lane];
                    float pG = red[(((wg * 4 + 2) * 4 + ri) << 5) + lane];
                    float pO = red[(((wg * 4 + 3) * 4 + ri) << 5) + lane];
                    float iv = acc[0][ri] + pI + bs[0][e];
                    float fv = acc[1][ri] + pF + bs[1][e];
                    float gv = acc[2][ri] + pG + bs[2][e];
                    float ov = acc[3][ri] + pO + bs[3][e];
                    float cn = sigm(fv) * cr[ri] + sigm(iv) * tanhf(gv);
                    cr[ri] = cn;
                    float h = sigm(ov) * tanhf(cn);
                    hh[e] = __float2half_rn(h);
                    hl[e] = __float2half_rn(h - __half2float(hh[e]));
                }
                *(__half2*)&Hhi[m * HID + n0] = __halves2half2(hh[0], hh[1]);
                *(__half2*)&Hlo[m * HID + n0] = __halves2half2(hl[0], hl[1]);
            }
        } else if (do_l0) {
            // ---- L0(t+1) epilogue ----
            const float* xp = g_xproj + (size_t)(t + 1) * BATCH * G4;
            __half* Hhi = g_h0hi[t & 1];
            __half* Hlo = g_h0lo[t & 1];
#pragma unroll
            for (int rr = 0; rr < 2; rr++) {
                int m = wg * 16 + qr + rr * 8;
                const float* xr = xp + (size_t)m * G4 + n0;
                float2 xi = *(const float2*)(xr);
                float2 xf = *(const float2*)(xr + 1024);
                float2 xg = *(const float2*)(xr + 2048);
                float2 xo = *(const float2*)(xr + 3072);
                __half hh[2], hl[2];
#pragma unroll
                for (int e = 0; e < 2; e++) {
                    int ri = rr * 2 + e;
                    float iv = acc[0][ri] + (e ? xi.y : xi.x);
                    float fv = acc[1][ri] + (e ? xf.y : xf.x);
                    float gv = acc[2][ri] + (e ? xg.y : xg.x);
                    float ov = acc[3][ri] + (e ? xo.y : xo.x);
                    float cn = sigm(fv) * cr[ri] + sigm(iv) * tanhf(gv);
                    cr[ri] = cn;
                    float h = sigm(ov) * tanhf(cn);
                    hh[e] = __float2half_rn(h);
                    hl[e] = __float2half_rn(h - __half2float(hh[e]));
                }
                *(__half2*)&Hhi[m * HID + n0] = __halves2half2(hh[0], hh[1]);
                *(__half2*)&Hlo[m * HID + n0] = __halves2half2(hl[0], hl[1]);
            }
        }
        grid_barrier(t + 1);
    }
}

// ===========================================================================
// xproj (round-5 validated, unchanged)
// ===========================================================================
__global__ void __launch_bounds__(256) xproj_kernel(
    const float* __restrict__ xs,
    const float* __restrict__ bih0, const float* __restrict__ bhh0)
{
    __shared__ __align__(16) __half sAhi[2][128][24];
    __shared__ __align__(16) __half sAlo[2][128][24];
    __shared__ uint4 sB[2][8][32];
    const int tid = threadIdx.x;
    const int nbx = blockIdx.x;
    const int mb  = blockIdx.y;
    const int w = tid >> 5, lane = tid & 31, qr = lane >> 2, qc = lane & 3;

    float acc[8][4];
#pragma unroll
    for (int j = 0; j < 8; j++)
#pragma unroll
        for (int k = 0; k < 4; k++) acc[j][k] = 0.f;

    const int srow = tid >> 1, sseg = tid & 1;
    const float* arow = xs + (size_t)(srow * 128 + TOFF + mb) * DIN + sseg * 8;

    float4 rf0, rf1;
    uint4 rb;
    auto ld = [&](int kt) {
        rf0 = *(const float4*)(arow + kt * 16);
        rf1 = *(const float4*)(arow + kt * 16 + 4);
        rb = g_wih0p[((size_t)(nbx * 8 + w) * 32 + kt) * 32 + lane];
    };
    ld(0);
#pragma unroll 1
    for (int kt = 0; kt < 32; kt++) {
        int s = kt & 1;
        __half2* dh = (__half2*)&sAhi[s][srow][sseg * 8];
        __half2* dl = (__half2*)&sAlo[s][srow][sseg * 8];
        float v[8] = {rf0.x, rf0.y, rf0.z, rf0.w, rf1.x, rf1.y, rf1.z, rf1.w};
#pragma unroll
        for (int p = 0; p < 4; p++) {
            float x0 = v[p * 2], x1 = v[p * 2 + 1];
            __half a0 = __float2half_rn(x0), a1 = __float2half_rn(x1);
            dh[p] = __halves2half2(a0, a1);
            dl[p] = __halves2half2(__float2half_rn(x0 - __half2float(a0)),
                                   __float2half_rn(x1 - __half2float(a1)));
        }
        sB[s][w][lane] = rb;
        __syncthreads();
        if (kt + 1 < 32) ld(kt + 1);
        {
            const int r = w * 16 + qr;
            u32 ah[4], al[4];
            ah[0] = *(const u32*)&sAhi[s][r][qc * 2];
            ah[1] = *(const u32*)&sAhi[s][r + 8][qc * 2];
            ah[2] = *(const u32*)&sAhi[s][r][qc * 2 + 8];
            ah[3] = *(const u32*)&sAhi[s][r + 8][qc * 2 + 8];
            al[0] = *(const u32*)&sAlo[s][r][qc * 2];
            al[1] = *(const u32*)&sAlo[s][r + 8][qc * 2];
            al[2] = *(const u32*)&sAlo[s][r][qc * 2 + 8];
            al[3] = *(const u32*)&sAlo[s][r + 8][qc * 2 + 8];
#pragma unroll
            for (int nt = 0; nt < 8; nt++) {
                uint4 bp = sB[s][nt][lane];
                u32 bh[2] = {bp.x, bp.y}, bl[2] = {bp.z, bp.w};
                mma_f16(acc[nt], ah, bh);
                mma_f16(acc[nt], al, bh);
                mma_f16(acc[nt], ah, bl);
            }
        }
        __syncthreads();
    }

    const int m0g = mb * 128 + w * 16 + qr;
#pragma unroll
    for (int nt = 0; nt < 8; nt++) {
        int colb = nbx * 64 + nt * 8 + qc * 2;
        float bv0 = bih0[colb] + bhh0[colb];
        float bv1 = bih0[colb + 1] + bhh0[colb + 1];
        *(float2*)&g_xproj[(size_t)m0g * G4 + colb] =
            make_float2(acc[nt][0] + bv0, acc[nt][1] + bv1);
        *(float2*)&g_xproj[(size_t)(m0g + 8) * G4 + colb] =
            make_float2(acc[nt][2] + bv0, acc[nt][3] + bv1);
    }
}

// ---------------- classifier (unchanged) ------------------------------------
__global__ void __launch_bounds__(256) classifier_kernel(
    const float* __restrict__ Wcls, const float* __restrict__ bcls,
    const float* __restrict__ dropu, float* __restrict__ out)
{
    int gw = (blockIdx.x * blockDim.x + threadIdx.x) >> 5;
    int lane = threadIdx.x & 31;
    int j = gw >> 5;
    int b0 = (gw & 31) * 4;
    const __half* hi = g_h1hi[0];
    const __half* lo = g_h1lo[0];

    float acc[4] = {0.f, 0.f, 0.f, 0.f};
#pragma unroll
    for (int it = 0; it < 8; ++it) {
        int h = it * 128 + lane * 4;
        float4 wv = *(const float4*)&Wcls[(size_t)j * HID + h];
#pragma unroll
        for (int bi = 0; bi < 4; ++bi) {
            int b = b0 + bi;
            int idx = b * HID + h;
            __half2 a0 = *(const __half2*)&hi[idx];
            __half2 a1 = *(const __half2*)&hi[idx + 2];
            __half2 c0 = *(const __half2*)&lo[idx];
            __half2 c1 = *(const __half2*)&lo[idx + 2];
            float2 f0 = __half22float2(a0), f1 = __half22float2(a1);
            float2 g0 = __half22float2(c0), g1 = __half22float2(c1);
            float x0 = f0.x + g0.x, x1 = f0.y + g0.y;
            float x2 = f1.x + g1.x, x3 = f1.y + g1.y;
            float4 u = *(const float4*)&dropu[(size_t)b * HID + h];
            acc[bi] += (u.x > 0.5f ? x0 : 0.f) * wv.x
                     + (u.y > 0.5f ? x1 : 0.f) * wv.y
                     + (u.z > 0.5f ? x2 : 0.f) * wv.z
                     + (u.w > 0.5f ? x3 : 0.f) * wv.w;
        }
    }
#pragma unroll
    for (int bi = 0; bi < 4; ++bi) {
        float v = acc[bi];
#pragma unroll
        for (int off = 16; off; off >>= 1)
            v += __shfl_xor_sync(0xffffffffu, v, off);
        if (lane == 0)
            out[(size_t)(b0 + bi) * 1000 + j] = 2.0f * v + bcls[j];
    }
}

// ---------------- launch ----------------------------------------------------
extern "C" void kernel_launch(void* const* d_in, const int* in_sizes, int n_in,
                              void* d_out, int out_size)
{
    const float* xs    = (const float*)d_in[0];
    const float* Wih0  = (const float*)d_in[1];
    const float* Whh0  = (const float*)d_in[2];
    const float* bih0  = (const float*)d_in[3];
    const float* bhh0  = (const float*)d_in[4];
    const float* Wih1  = (const float*)d_in[5];
    const float* Whh1  = (const float*)d_in[6];
    const float* bih1  = (const float*)d_in[7];
    const float* bhh1  = (const float*)d_in[8];
    const float* Wcls  = (const float*)d_in[9];
    const float* bcls  = (const float*)d_in[10];
    const float* dropu = (const float*)d_in[11];
    float* out = (float*)d_out;

    cudaFuncSetAttribute(step_persist, cudaFuncAttributeMaxDynamicSharedMemorySize, PS_TOTAL);

    init_states<<<(BATCH * HID + 255) / 256, 256>>>();
    pack_all<<<(3 * PACK_N64 + PACK_N32) / 256, 256>>>(Whh0, Wih1, Whh1, Wih0);
    xproj_kernel<<<dim3(64, 64), 256>>>(xs, bih0, bhh0);
    step_persist<<<128, 512, PS_TOTAL>>>(bih1, bhh1);
    classifier_kernel<<<4000, 256>>>(Wcls, bcls, dropu, out);
}

// round 8
// speedup vs baseline: 1.2165x; 1.1640x over previous
#include <cuda_runtime.h>
#include <cuda_fp16.h>

#define BATCH 128
#define DIN   512
#define HID   1024
#define G4    4096
#define STEPS 64
#define TOFF  55   // (128 - 64 - 9)

typedef unsigned int u32;

// ---------------- device scratch (no allocations allowed) -----------------
__device__ float  g_xproj[(size_t)STEPS * BATCH * G4];
__device__ __half g_h0hi[2][BATCH * HID], g_h0lo[2][BATCH * HID];
__device__ __half g_h1hi[2][BATCH * HID], g_h1lo[2][BATCH * HID];
__device__ float  g_c0[BATCH * HID];
__device__ uint4  g_whh0p[(size_t)512 * 64 * 32];
__device__ uint4  g_wih1p[(size_t)512 * 64 * 32];
__device__ uint4  g_whh1p[(size_t)512 * 64 * 32];
__device__ uint4  g_wih0p[(size_t)512 * 32 * 32];
__device__ u32    g_bar_count, g_bar_gen;

__device__ __forceinline__ float sigm(float x) { return 1.0f / (1.0f + expf(-x)); }
__device__ __forceinline__ u32 h2u(__half2 h) { return *(u32*)&h; }

__device__ __forceinline__ void mma_f16(float* d, const u32* a, const u32* b) {
    asm volatile("mma.sync.aligned.m16n8k16.row.col.f32.f16.f16.f32 "
        "{%0,%1,%2,%3},{%4,%5,%6,%7},{%8,%9},{%0,%1,%2,%3};"
        : "+f"(d[0]), "+f"(d[1]), "+f"(d[2]), "+f"(d[3])
        : "r"(a[0]), "r"(a[1]), "r"(a[2]), "r"(a[3]), "r"(b[0]), "r"(b[1]));
}
__device__ __forceinline__ u32 smem_u32(const void* p) {
    u32 a;
    asm("{ .reg .u64 t; cvta.to.shared.u64 t, %1; cvt.u32.u64 %0, t; }" : "=r"(a) : "l"(p));
    return a;
}
__device__ __forceinline__ void cpa16(u32 dst, const void* src) {
    asm volatile("cp.async.cg.shared.global [%0], [%1], 16;"
                 :: "r"(dst), "l"(__cvta_generic_to_global(src)) : "memory");
}
__device__ __forceinline__ void cpa_commit() {
    asm volatile("cp.async.commit_group;" ::: "memory");
}
template<int N> __device__ __forceinline__ void cpa_wait() {
    asm volatile("cp.async.wait_group %0;" :: "n"(N) : "memory");
}
__device__ __forceinline__ void ldm4(u32* r, u32 addr) {
    asm volatile("ldmatrix.sync.aligned.m8n8.x4.shared.b16 {%0,%1,%2,%3}, [%4];"
        : "=r"(r[0]), "=r"(r[1]), "=r"(r[2]), "=r"(r[3]) : "r"(addr));
}

// smem stage layout (53248 B per stage, 4 stages = 212992 B):
//  +0      A0hi (10240 = 128 rows x 80B, 64B data = K32)
//  +10240  A0lo   +20480  A1hi   +30720  A1lo
//  +40960  B: mat0(wih1) 4096 | mat1(whh1) 4096 | mat2(whh0) 4096
#define ST_SZ    53248
#define ST_B     40960
#define PS_TOTAL (4 * ST_SZ)

// ---------------- grid-wide software barrier (128 CTAs) --------------------
__device__ __forceinline__ void grid_barrier(int gen) {
    __syncthreads();
    if (threadIdx.x == 0) {
        __threadfence();
        u32 prev = atomicAdd(&g_bar_count, 1u);
        if (prev == (u32)(gen * 128 + 127)) {
            atomicExch(&g_bar_gen, (u32)(gen + 1));
        } else {
            u32 g;
            do {
                __nanosleep(64);
                asm volatile("ld.acquire.gpu.u32 %0, [%1];"
                             : "=r"(g) : "l"((const u32*)&g_bar_gen));
            } while (g <= (u32)gen);
        }
    }
    __syncthreads();
}

// ---------------- init states ----------------------------------------------
__global__ void init_states() {
    int i = blockIdx.x * blockDim.x + threadIdx.x;
    if (i == 0) { g_bar_count = 0u; g_bar_gen = 0u; }
    if (i < BATCH * HID) {
        __half z = __float2half(0.f);
        g_h0hi[0][i] = z; g_h0lo[0][i] = z; g_h0hi[1][i] = z; g_h0lo[1][i] = z;
        g_h1hi[0][i] = z; g_h1lo[0][i] = z; g_h1hi[1][i] = z; g_h1lo[1][i] = z;
        g_c0[i] = 0.f;
    }
}

// ---------------- weight packer (single launch) ----------------------------
__device__ __forceinline__ void pack_one(
    const float* __restrict__ W, uint4* __restrict__ dst, int Kt, int idx)
{
    int lane = idx & 31;
    int rest = idx >> 5;
    int kt = rest % Kt, nt = rest / Kt;
    int K = Kt * 16;
    int n = nt * 8 + (lane >> 2);
    int k0 = kt * 16 + (lane & 3) * 2;
    const float* wr = W + (size_t)n * K + k0;
    float w00 = wr[0], w01 = wr[1], w10 = wr[8], w11 = wr[9];
    __half h00 = __float2half_rn(w00), h01 = __float2half_rn(w01);
    __half h10 = __float2half_rn(w10), h11 = __float2half_rn(w11);
    uint4 v;
    v.x = h2u(__halves2half2(h00, h01));
    v.y = h2u(__halves2half2(h10, h11));
    v.z = h2u(__halves2half2(__float2half_rn(w00 - __half2float(h00)),
                             __float2half_rn(w01 - __half2float(h01))));
    v.w = h2u(__halves2half2(__float2half_rn(w10 - __half2float(h10)),
                             __float2half_rn(w11 - __half2float(h11))));
    dst[idx] = v;
}
#define PACK_N64 (512 * 64 * 32)
#define PACK_N32 (512 * 32 * 32)
__global__ void pack_all(const float* __restrict__ Whh0, const float* __restrict__ Wih1,
                         const float* __restrict__ Whh1, const float* __restrict__ Wih0) {
    int idx = blockIdx.x * 256 + threadIdx.x;
    if (idx < PACK_N64)               pack_one(Whh0, g_whh0p, 64, idx);
    else if (idx < 2 * PACK_N64)      pack_one(Wih1, g_wih1p, 64, idx - PACK_N64);
    else if (idx < 3 * PACK_N64)      pack_one(Whh1, g_whh1p, 64, idx - 2 * PACK_N64);
    else                              pack_one(Wih0, g_wih0p, 32, idx - 3 * PACK_N64);
}

// ===========================================================================
// Persistent fused-step kernel. Grid 128, 256 threads = 8 warps.
// Warp w owns mtile w (rows w*16..+15), all 4 gates, both output layers.
// Step t: acc1 = h0(t+1)@Wih1 + h1(t)@Whh1 (-> L1(t)); acc0 = h0(t+1)@Whh0
// (-> L0(t+1)). Single uniform loop: 32 K32-chunks, all 3 matrices per chunk.
// 4-stage cp.async pipeline, sync every 2 chunks.
// ===========================================================================
__global__ void __launch_bounds__(256) step_persist(
    const float* __restrict__ bih1, const float* __restrict__ bhh1)
{
    extern __shared__ char smem[];
    const int tid = threadIdx.x, bx = blockIdx.x;
    const int w = tid >> 5, lane = tid & 31, qr = lane >> 2, qc = lane & 3;
    const u32 sb = smem_u32(smem);
    const int n0 = bx * 8 + qc * 2;

    // ---- prologue: L0 step 0 (h0 = 0) on this CTA's 8 columns ----
    for (int i = tid; i < 128 * 8; i += 256) {
        int m = i >> 3, u = i & 7;
        int n = bx * 8 + u;
        const float* xr = g_xproj + (size_t)m * G4;
        float iv = xr[n], gv = xr[2048 + n], ov = xr[3072 + n];
        float cn = sigm(iv) * tanhf(gv);
        g_c0[m * HID + n] = cn;
        float h = sigm(ov) * tanhf(cn);
        __half hh = __float2half_rn(h);
        g_h0hi[1][m * HID + n] = hh;
        g_h0lo[1][m * HID + n] = __float2half_rn(h - __half2float(hh));
    }
    grid_barrier(0);

    // biases (L1) in regs
    float bs[4][2];
#pragma unroll
    for (int g = 0; g < 4; g++) {
        bs[g][0] = bih1[g * 1024 + n0] + bhh1[g * 1024 + n0];
        bs[g][1] = bih1[g * 1024 + n0 + 1] + bhh1[g * 1024 + n0 + 1];
    }
    // c-states in regs: cr1 (layer1, zeros) and cr0 (layer0, from prologue)
    float cr1[4] = {0.f, 0.f, 0.f, 0.f};
    float cr0[4];
#pragma unroll
    for (int rr = 0; rr < 2; rr++) {
        int m = w * 16 + qr + rr * 8;
        cr0[rr * 2 + 0] = g_c0[m * HID + n0];
        cr0[rr * 2 + 1] = g_c0[m * HID + n0 + 1];
    }

    // ---- invariant staging coords ----
    // A: 8 cp16/thread: idx = tid + i*256 -> plane(0..3), row, seg
    u32 adst[8]; u32 arow[8]; int aplane[8]; int aseg[8];
#pragma unroll
    for (int i = 0; i < 8; i++) {
        int idx = tid + i * 256;
        aplane[i] = idx >> 9;
        arow[i] = (idx >> 2) & 127;
        aseg[i] = idx & 3;
        adst[i] = sb + aplane[i] * 10240 + arow[i] * 80 + aseg[i] * 16;
    }
    // B: 3 cp16/thread (mat = i). (nt,sub) = (w>>1, w&1)
    const u32 bdst0 = sb + ST_B + (tid << 4);
    const size_t bsrc0 = (((size_t)((w >> 1) * 128 + bx)) * 64 + (w & 1)) * 32 + lane;
    // A fragment base (ldmatrix) for this warp's mtile
    const u32 aF = sb + (w * 16 + (lane & 15)) * 80 + ((lane >> 4) * 16);

#pragma unroll 1
    for (int t = 0; t < STEPS; t++) {
        const int do_l0 = (t < STEPS - 1);
        const __half* Ap0 = g_h0hi[(t + 1) & 1];   // plane 0
        const __half* Ap1 = g_h0lo[(t + 1) & 1];   // plane 1
        const __half* Ap2 = g_h1hi[t & 1];         // plane 2
        const __half* Ap3 = g_h1lo[t & 1];         // plane 3

        float acc1[4][4], acc0[4][4];
#pragma unroll
        for (int j = 0; j < 4; j++)
#pragma unroll
            for (int k = 0; k < 4; k++) { acc1[j][k] = 0.f; acc0[j][k] = 0.f; }

        auto issue = [&](int kk) {
            const u32 soff = (u32)(kk & 3) * ST_SZ;
#pragma unroll
            for (int i = 0; i < 8; i++) {
                const __half* base = (aplane[i] == 0) ? Ap0 :
                                     (aplane[i] == 1) ? Ap1 :
                                     (aplane[i] == 2) ? Ap2 : Ap3;
                cpa16(adst[i] + soff,
                      base + (size_t)arow[i] * HID + kk * 32 + aseg[i] * 8);
            }
            cpa16(bdst0 + soff,           g_wih1p + bsrc0 + (size_t)kk * 64);
            cpa16(bdst0 + soff + 4096,    g_whh1p + bsrc0 + (size_t)kk * 64);
            cpa16(bdst0 + soff + 8192,    g_whh0p + bsrc0 + (size_t)kk * 64);
        };

        issue(0); cpa_commit();
        issue(1); cpa_commit();

#pragma unroll 1
        for (int kk = 0; kk < 32; kk += 2) {
            cpa_wait<0>();
            __syncthreads();
            if (kk + 2 < 32) {
                issue(kk + 2); cpa_commit();
                issue(kk + 3); cpa_commit();
            }
#pragma unroll
            for (int half = 0; half < 2; half++) {
                const int s = (kk + half) & 3;
                const u32 aBase = aF + (u32)s * ST_SZ;
                const uint4* bst = (const uint4*)(smem + (size_t)s * ST_SZ + ST_B);
#pragma unroll
                for (int sub = 0; sub < 2; sub++) {
                    u32 a0h[4], a0l[4], a1h[4], a1l[4];
                    ldm4(a0h, aBase + sub * 32);
                    ldm4(a0l, aBase + sub * 32 + 10240);
                    ldm4(a1h, aBase + sub * 32 + 20480);
                    ldm4(a1l, aBase + sub * 32 + 30720);
#pragma unroll
                    for (int nt = 0; nt < 4; nt++) {
                        const int bi = (nt * 2 + sub) * 32 + lane;
                        uint4 b0 = bst[bi];
                        uint4 b1 = bst[256 + bi];
                        uint4 b2 = bst[512 + bi];
                        u32 b0h[2] = {b0.x, b0.y}, b0l[2] = {b0.z, b0.w};
                        u32 b1h[2] = {b1.x, b1.y}, b1l[2] = {b1.z, b1.w};
                        u32 b2h[2] = {b2.x, b2.y}, b2l[2] = {b2.z, b2.w};
                        mma_f16(acc1[nt], a0h, b0h);
                        mma_f16(acc1[nt], a0l, b0h);
                        mma_f16(acc1[nt], a0h, b0l);
                        mma_f16(acc1[nt], a1h, b1h);
                        mma_f16(acc1[nt], a1l, b1h);
                        mma_f16(acc1[nt], a1h, b1l);
                        mma_f16(acc0[nt], a0h, b2h);
                        mma_f16(acc0[nt], a0l, b2h);
                        mma_f16(acc0[nt], a0h, b2l);
                    }
                }
            }
        }

        // ---- L1(t) epilogue ----
        {
            __half* Hhi = g_h1hi[(t + 1) & 1];
            __half* Hlo = g_h1lo[(t + 1) & 1];
#pragma unroll
            for (int rr = 0; rr < 2; rr++) {
                int m = w * 16 + qr + rr * 8;
                __half hh[2], hl[2];
#pragma unroll
                for (int e = 0; e < 2; e++) {
                    int ri = rr * 2 + e;
                    float iv = acc1[0][ri] + bs[0][e];
                    float fv = acc1[1][ri] + bs[1][e];
                    float gv = acc1[2][ri] + bs[2][e];
                    float ov = acc1[3][ri] + bs[3][e];
                    float cn = sigm(fv) * cr1[ri] + sigm(iv) * tanhf(gv);
                    cr1[ri] = cn;
                    float h = sigm(ov) * tanhf(cn);
                    hh[e] = __float2half_rn(h);
                    hl[e] = __float2half_rn(h - __half2float(hh[e]));
                }
                *(__half2*)&Hhi[m * HID + n0] = __halves2half2(hh[0], hh[1]);
                *(__half2*)&Hlo[m * HID + n0] = __halves2half2(hl[0], hl[1]);
            }
        }
        // ---- L0(t+1) epilogue ----
        if (do_l0) {
            const float* xp = g_xproj + (size_t)(t + 1) * BATCH * G4;
            __half* Hhi = g_h0hi[t & 1];
            __half* Hlo = g_h0lo[t & 1];
#pragma unroll
            for (int rr = 0; rr < 2; rr++) {
                int m = w * 16 + qr + rr * 8;
                const float* xr = xp + (size_t)m * G4 + n0;
                float2 xi = *(const float2*)(xr);
                float2 xf = *(const float2*)(xr + 1024);
                float2 xg = *(const float2*)(xr + 2048);
                float2 xo = *(const float2*)(xr + 3072);
                __half hh[2], hl[2];
#pragma unroll
                for (int e = 0; e < 2; e++) {
                    int ri = rr * 2 + e;
                    float iv = acc0[0][ri] + (e ? xi.y : xi.x);
                    float fv = acc0[1][ri] + (e ? xf.y : xf.x);
                    float gv = acc0[2][ri] + (e ? xg.y : xg.x);
                    float ov = acc0[3][ri] + (e ? xo.y : xo.x);
                    float cn = sigm(fv) * cr0[ri] + sigm(iv) * tanhf(gv);
                    cr0[ri] = cn;
                    float h = sigm(ov) * tanhf(cn);
                    hh[e] = __float2half_rn(h);
                    hl[e] = __float2half_rn(h - __half2float(hh[e]));
                }
                *(__half2*)&Hhi[m * HID + n0] = __halves2half2(hh[0], hh[1]);
                *(__half2*)&Hlo[m * HID + n0] = __halves2half2(hl[0], hl[1]);
            }
        }
        grid_barrier(t + 1);
    }
}

// ===========================================================================
// xproj (round-5 validated, unchanged)
// ===========================================================================
__global__ void __launch_bounds__(256) xproj_kernel(
    const float* __restrict__ xs,
    const float* __restrict__ bih0, const float* __restrict__ bhh0)
{
    __shared__ __align__(16) __half sAhi[2][128][24];
    __shared__ __align__(16) __half sAlo[2][128][24];
    __shared__ uint4 sB[2][8][32];
    const int tid = threadIdx.x;
    const int nbx = blockIdx.x;
    const int mb  = blockIdx.y;
    const int w = tid >> 5, lane = tid & 31, qr = lane >> 2, qc = lane & 3;

    float acc[8][4];
#pragma unroll
    for (int j = 0; j < 8; j++)
#pragma unroll
        for (int k = 0; k < 4; k++) acc[j][k] = 0.f;

    const int srow = tid >> 1, sseg = tid & 1;
    const float* arow = xs + (size_t)(srow * 128 + TOFF + mb) * DIN + sseg * 8;

    float4 rf0, rf1;
    uint4 rb;
    auto ld = [&](int kt) {
        rf0 = *(const float4*)(arow + kt * 16);
        rf1 = *(const float4*)(arow + kt * 16 + 4);
        rb = g_wih0p[((size_t)(nbx * 8 + w) * 32 + kt) * 32 + lane];
    };
    ld(0);
#pragma unroll 1
    for (int kt = 0; kt < 32; kt++) {
        int s = kt & 1;
        __half2* dh = (__half2*)&sAhi[s][srow][sseg * 8];
        __half2* dl = (__half2*)&sAlo[s][srow][sseg * 8];
        float v[8] = {rf0.x, rf0.y, rf0.z, rf0.w, rf1.x, rf1.y, rf1.z, rf1.w};
#pragma unroll
        for (int p = 0; p < 4; p++) {
            float x0 = v[p * 2], x1 = v[p * 2 + 1];
            __half a0 = __float2half_rn(x0), a1 = __float2half_rn(x1);
            dh[p] = __halves2half2(a0, a1);
            dl[p] = __halves2half2(__float2half_rn(x0 - __half2float(a0)),
                                   __float2half_rn(x1 - __half2float(a1)));
        }
        sB[s][w][lane] = rb;
        __syncthreads();
        if (kt + 1 < 32) ld(kt + 1);
        {
            const int r = w * 16 + qr;
            u32 ah[4], al[4];
            ah[0] = *(const u32*)&sAhi[s][r][qc * 2];
            ah[1] = *(const u32*)&sAhi[s][r + 8][qc * 2];
            ah[2] = *(const u32*)&sAhi[s][r][qc * 2 + 8];
            ah[3] = *(const u32*)&sAhi[s][r + 8][qc * 2 + 8];
            al[0] = *(const u32*)&sAlo[s][r][qc * 2];
            al[1] = *(const u32*)&sAlo[s][r + 8][qc * 2];
            al[2] = *(const u32*)&sAlo[s][r][qc * 2 + 8];
            al[3] = *(const u32*)&sAlo[s][r + 8][qc * 2 + 8];
#pragma unroll
            for (int nt = 0; nt < 8; nt++) {
                uint4 bp = sB[s][nt][lane];
                u32 bh[2] = {bp.x, bp.y}, bl[2] = {bp.z, bp.w};
                mma_f16(acc[nt], ah, bh);
                mma_f16(acc[nt], al, bh);
                mma_f16(acc[nt], ah, bl);
            }
        }
        __syncthreads();
    }

    const int m0g = mb * 128 + w * 16 + qr;
#pragma unroll
    for (int nt = 0; nt < 8; nt++) {
        int colb = nbx * 64 + nt * 8 + qc * 2;
        float bv0 = bih0[colb] + bhh0[colb];
        float bv1 = bih0[colb + 1] + bhh0[colb + 1];
        *(float2*)&g_xproj[(size_t)m0g * G4 + colb] =
            make_float2(acc[nt][0] + bv0, acc[nt][1] + bv1);
        *(float2*)&g_xproj[(size_t)(m0g + 8) * G4 + colb] =
            make_float2(acc[nt][2] + bv0, acc[nt][3] + bv1);
    }
}

// ---------------- classifier (unchanged) ------------------------------------
__global__ void __launch_bounds__(256) classifier_kernel(
    const float* __restrict__ Wcls, const float* __restrict__ bcls,
    const float* __restrict__ dropu, float* __restrict__ out)
{
    int gw = (blockIdx.x * blockDim.x + threadIdx.x) >> 5;
    int lane = threadIdx.x & 31;
    int j = gw >> 5;
    int b0 = (gw & 31) * 4;
    const __half* hi = g_h1hi[0];
    const __half* lo = g_h1lo[0];

    float acc[4] = {0.f, 0.f, 0.f, 0.f};
#pragma unroll
    for (int it = 0; it < 8; ++it) {
        int h = it * 128 + lane * 4;
        float4 wv = *(const float4*)&Wcls[(size_t)j * HID + h];
#pragma unroll
        for (int bi = 0; bi < 4; ++bi) {
            int b = b0 + bi;
            int idx = b * HID + h;
            __half2 a0 = *(const __half2*)&hi[idx];
            __half2 a1 = *(const __half2*)&hi[idx + 2];
            __half2 c0 = *(const __half2*)&lo[idx];
            __half2 c1 = *(const __half2*)&lo[idx + 2];
            float2 f0 = __half22float2(a0), f1 = __half22float2(a1);
            float2 g0 = __half22float2(c0), g1 = __half22float2(c1);
            float x0 = f0.x + g0.x, x1 = f0.y + g0.y;
            float x2 = f1.x + g1.x, x3 = f1.y + g1.y;
            float4 u = *(const float4*)&dropu[(size_t)b * HID + h];
            acc[bi] += (u.x > 0.5f ? x0 : 0.f) * wv.x
                     + (u.y > 0.5f ? x1 : 0.f) * wv.y
                     + (u.z > 0.5f ? x2 : 0.f) * wv.z
                     + (u.w > 0.5f ? x3 : 0.f) * wv.w;
        }
    }
#pragma unroll
    for (int bi = 0; bi < 4; ++bi) {
        float v = acc[bi];
#pragma unroll
        for (int off = 16; off; off >>= 1)
            v += __shfl_xor_sync(0xffffffffu, v, off);
        if (lane == 0)
            out[(size_t)(b0 + bi) * 1000 + j] = 2.0f * v + bcls[j];
    }
}

// ---------------- launch ----------------------------------------------------
extern "C" void kernel_launch(void* const* d_in, const int* in_sizes, int n_in,
                              void* d_out, int out_size)
{
    const float* xs    = (const float*)d_in[0];
    const float* Wih0  = (const float*)d_in[1];
    const float* Whh0  = (const float*)d_in[2];
    const float* bih0  = (const float*)d_in[3];
    const float* bhh0  = (const float*)d_in[4];
    const float* Wih1  = (const float*)d_in[5];
    const float* Whh1  = (const float*)d_in[6];
    const float* bih1  = (const float*)d_in[7];
    const float* bhh1  = (const float*)d_in[8];
    const float* Wcls  = (const float*)d_in[9];
    const float* bcls  = (const float*)d_in[10];
    const float* dropu = (const float*)d_in[11];
    float* out = (float*)d_out;

    cudaFuncSetAttribute(step_persist, cudaFuncAttributeMaxDynamicSharedMemorySize, PS_TOTAL);

    init_states<<<(BATCH * HID + 255) / 256, 256>>>();
    pack_all<<<(3 * PACK_N64 + PACK_N32) / 256, 256>>>(Whh0, Wih1, Whh1, Wih0);
    xproj_kernel<<<dim3(64, 64), 256>>>(xs, bih0, bhh0);
    step_persist<<<128, 256, PS_TOTAL>>>(bih1, bhh1);
    classifier_kernel<<<4000, 256>>>(Wcls, bcls, dropu, out);
}

// round 9
// speedup vs baseline: 1.3024x; 1.0706x over previous
#include <cuda_runtime.h>
#include <cuda_fp16.h>

#define BATCH 128
#define DIN   512
#define HID   1024
#define G4    4096
#define STEPS 64
#define TOFF  55   // (128 - 64 - 9)

typedef unsigned int u32;

// ---------------- device scratch (no allocations allowed) -----------------
__device__ float  g_xproj[(size_t)STEPS * BATCH * G4];
__device__ __half g_h0hi[2][BATCH * HID], g_h0lo[2][BATCH * HID];
__device__ __half g_h1hi[2][BATCH * HID], g_h1lo[2][BATCH * HID];
__device__ float  g_c0[BATCH * HID];
__device__ uint4  g_whh0p[(size_t)512 * 64 * 32];
__device__ uint4  g_wih1p[(size_t)512 * 64 * 32];
__device__ uint4  g_whh1p[(size_t)512 * 64 * 32];
__device__ uint4  g_wih0p[(size_t)512 * 32 * 32];
__device__ u32    g_bar_count, g_bar_gen;

__device__ __forceinline__ float sigm(float x) { return 1.0f / (1.0f + expf(-x)); }
__device__ __forceinline__ u32 h2u(__half2 h) { return *(u32*)&h; }

__device__ __forceinline__ void mma_f16(float* d, const u32* a, const u32* b) {
    asm volatile("mma.sync.aligned.m16n8k16.row.col.f32.f16.f16.f32 "
        "{%0,%1,%2,%3},{%4,%5,%6,%7},{%8,%9},{%0,%1,%2,%3};"
        : "+f"(d[0]), "+f"(d[1]), "+f"(d[2]), "+f"(d[3])
        : "r"(a[0]), "r"(a[1]), "r"(a[2]), "r"(a[3]), "r"(b[0]), "r"(b[1]));
}
__device__ __forceinline__ u32 smem_u32(const void* p) {
    u32 a;
    asm("{ .reg .u64 t; cvta.to.shared.u64 t, %1; cvt.u32.u64 %0, t; }" : "=r"(a) : "l"(p));
    return a;
}
__device__ __forceinline__ void cpa16(u32 dst, const void* src) {
    asm volatile("cp.async.cg.shared.global [%0], [%1], 16;"
                 :: "r"(dst), "l"(__cvta_generic_to_global(src)) : "memory");
}
__device__ __forceinline__ void cpa_commit() {
    asm volatile("cp.async.commit_group;" ::: "memory");
}
template<int N> __device__ __forceinline__ void cpa_wait() {
    asm volatile("cp.async.wait_group %0;" :: "n"(N) : "memory");
}
__device__ __forceinline__ void ldm4(u32* r, u32 addr) {
    asm volatile("ldmatrix.sync.aligned.m8n8.x4.shared.b16 {%0,%1,%2,%3}, [%4];"
        : "=r"(r[0]), "=r"(r[1]), "=r"(r[2]), "=r"(r[3]) : "r"(addr));
}

// smem stage layout (53248 B per stage, 4 stages = 212992 B):
//  +0      A0hi (10240 = 128 rows x 80B, 64B data = K32)
//  +10240  A0lo   +20480  A1hi   +30720  A1lo
//  +40960  B: mat0(wih1) 4096 | mat1(whh1) 4096 | mat2(whh0) 4096
#define ST_SZ    53248
#define ST_B     40960
#define PS_TOTAL (4 * ST_SZ)

// ---------------- grid-wide software barrier (128 CTAs) --------------------
__device__ __forceinline__ void grid_barrier(int gen) {
    __syncthreads();
    if (threadIdx.x == 0) {
        __threadfence();
        u32 prev = atomicAdd(&g_bar_count, 1u);
        if (prev == (u32)(gen * 128 + 127)) {
            atomicExch(&g_bar_gen, (u32)(gen + 1));
        } else {
            u32 g;
            do {
                __nanosleep(64);
                asm volatile("ld.acquire.gpu.u32 %0, [%1];"
                             : "=r"(g) : "l"((const u32*)&g_bar_gen));
            } while (g <= (u32)gen);
        }
    }
    __syncthreads();
}

// ---------------- init states ----------------------------------------------
__global__ void init_states() {
    int i = blockIdx.x * blockDim.x + threadIdx.x;
    if (i == 0) { g_bar_count = 0u; g_bar_gen = 0u; }
    if (i < BATCH * HID) {
        __half z = __float2half(0.f);
        g_h0hi[0][i] = z; g_h0lo[0][i] = z; g_h0hi[1][i] = z; g_h0lo[1][i] = z;
        g_h1hi[0][i] = z; g_h1lo[0][i] = z; g_h1hi[1][i] = z; g_h1lo[1][i] = z;
        g_c0[i] = 0.f;
    }
}

// ---------------- weight packer (single launch) ----------------------------
__device__ __forceinline__ void pack_one(
    const float* __restrict__ W, uint4* __restrict__ dst, int Kt, int idx)
{
    int lane = idx & 31;
    int rest = idx >> 5;
    int kt = rest % Kt, nt = rest / Kt;
    int K = Kt * 16;
    int n = nt * 8 + (lane >> 2);
    int k0 = kt * 16 + (lane & 3) * 2;
    const float* wr = W + (size_t)n * K + k0;
    float w00 = wr[0], w01 = wr[1], w10 = wr[8], w11 = wr[9];
    __half h00 = __float2half_rn(w00), h01 = __float2half_rn(w01);
    __half h10 = __float2half_rn(w10), h11 = __float2half_rn(w11);
    uint4 v;
    v.x = h2u(__halves2half2(h00, h01));
    v.y = h2u(__halves2half2(h10, h11));
    v.z = h2u(__halves2half2(__float2half_rn(w00 - __half2float(h00)),
                             __float2half_rn(w01 - __half2float(h01))));
    v.w = h2u(__halves2half2(__float2half_rn(w10 - __half2float(h10)),
                             __float2half_rn(w11 - __half2float(h11))));
    dst[idx] = v;
}
#define PACK_N64 (512 * 64 * 32)
#define PACK_N32 (512 * 32 * 32)
__global__ void pack_all(const float* __restrict__ Whh0, const float* __restrict__ Wih1,
                         const float* __restrict__ Whh1, const float* __restrict__ Wih0) {
    int idx = blockIdx.x * 256 + threadIdx.x;
    if (idx < PACK_N64)               pack_one(Whh0, g_whh0p, 64, idx);
    else if (idx < 2 * PACK_N64)      pack_one(Wih1, g_wih1p, 64, idx - PACK_N64);
    else if (idx < 3 * PACK_N64)      pack_one(Whh1, g_whh1p, 64, idx - 2 * PACK_N64);
    else                              pack_one(Wih0, g_wih0p, 32, idx - 3 * PACK_N64);
}

// ===========================================================================
// Persistent fused-step kernel. Grid 128, 512 threads = 16 warps.
// wg = w&7 -> mtile (rows wg*16..+15); ng = w>>3 -> job:
//   ng0: acc1 = h0(t+1)@Wih1 + h1(t)@Whh1  (6 MMA/nt)  -> L1(t) epilogue
//   ng1: acc0 = h0(t+1)@Whh0               (3 MMA/nt)  -> L0(t+1) epilogue
// Disjoint outputs => no cross-warp reduction. Uniform 32-chunk K loop,
// 4-stage cp.async, sync every 2 chunks. c-states & biases in registers.
// ===========================================================================
__global__ void __launch_bounds__(512) step_persist(
    const float* __restrict__ bih1, const float* __restrict__ bhh1)
{
    extern __shared__ char smem[];
    const int tid = threadIdx.x, bx = blockIdx.x;
    const int w = tid >> 5, lane = tid & 31, qr = lane >> 2, qc = lane & 3;
    const int wg = w & 7, ng = w >> 3;
    const u32 sb = smem_u32(smem);
    const int n0 = bx * 8 + qc * 2;

    // ---- prologue: L0 step 0 (h0 = 0) on this CTA's 8 columns ----
    for (int i = tid; i < 128 * 8; i += 512) {
        int m = i >> 3, u = i & 7;
        int n = bx * 8 + u;
        const float* xr = g_xproj + (size_t)m * G4;
        float iv = xr[n], gv = xr[2048 + n], ov = xr[3072 + n];
        float cn = sigm(iv) * tanhf(gv);
        g_c0[m * HID + n] = cn;
        float h = sigm(ov) * tanhf(cn);
        __half hh = __float2half_rn(h);
        g_h0hi[1][m * HID + n] = hh;
        g_h0lo[1][m * HID + n] = __float2half_rn(h - __half2float(hh));
    }
    grid_barrier(0);

    // biases (L1) in regs (used by ng0 only)
    float bs[4][2];
#pragma unroll
    for (int g = 0; g < 4; g++) {
        bs[g][0] = bih1[g * 1024 + n0] + bhh1[g * 1024 + n0];
        bs[g][1] = bih1[g * 1024 + n0 + 1] + bhh1[g * 1024 + n0 + 1];
    }
    // c-state in regs: ng0 -> c1 (zeros), ng1 -> c0 (from prologue)
    float cr[4] = {0.f, 0.f, 0.f, 0.f};
    if (ng == 1) {
#pragma unroll
        for (int rr = 0; rr < 2; rr++) {
            int m = wg * 16 + qr + rr * 8;
            cr[rr * 2 + 0] = g_c0[m * HID + n0];
            cr[rr * 2 + 1] = g_c0[m * HID + n0 + 1];
        }
    }

    // ---- invariant staging coords ----
    // A: 4 cp16/thread: idx = tid + i*512 -> plane(0..3), row, seg
    u32 adst[4]; u32 arow[4]; int aplane[4]; int aseg[4];
#pragma unroll
    for (int i = 0; i < 4; i++) {
        int idx = tid + i * 512;
        aplane[i] = idx >> 9;
        arow[i] = (idx >> 2) & 127;
        aseg[i] = idx & 3;
        adst[i] = sb + aplane[i] * 10240 + arow[i] * 80 + aseg[i] * 16;
    }
    // B: threads 0..255 do 3 cp16 (one per matrix); (nt,sub) = (tw>>1, tw&1)
    const bool doB = (tid < 256);
    const int tw = tid >> 5;  // 0..7 when doB
    const u32 bdst0 = sb + ST_B + (tid << 4);
    const size_t bsrc0 = (((size_t)((tw >> 1) * 128 + bx)) * 64 + (tw & 1)) * 32 + lane;
    // A fragment base (ldmatrix) for this warp's mtile
    const u32 aF = sb + (wg * 16 + (lane & 15)) * 80 + ((lane >> 4) * 16);

#pragma unroll 1
    for (int t = 0; t < STEPS; t++) {
        const int do_l0 = (t < STEPS - 1);
        const __half* Ap0 = g_h0hi[(t + 1) & 1];   // plane 0
        const __half* Ap1 = g_h0lo[(t + 1) & 1];   // plane 1
        const __half* Ap2 = g_h1hi[t & 1];         // plane 2
        const __half* Ap3 = g_h1lo[t & 1];         // plane 3

        float acc[4][4];
#pragma unroll
        for (int j = 0; j < 4; j++)
#pragma unroll
            for (int k = 0; k < 4; k++) acc[j][k] = 0.f;

        auto issue = [&](int kk) {
            const u32 soff = (u32)(kk & 3) * ST_SZ;
#pragma unroll
            for (int i = 0; i < 4; i++) {
                const __half* base = (aplane[i] == 0) ? Ap0 :
                                     (aplane[i] == 1) ? Ap1 :
                                     (aplane[i] == 2) ? Ap2 : Ap3;
                cpa16(adst[i] + soff,
                      base + (size_t)arow[i] * HID + kk * 32 + aseg[i] * 8);
            }
            if (doB) {
                cpa16(bdst0 + soff,        g_wih1p + bsrc0 + (size_t)kk * 64);
                cpa16(bdst0 + soff + 4096, g_whh1p + bsrc0 + (size_t)kk * 64);
                cpa16(bdst0 + soff + 8192, g_whh0p + bsrc0 + (size_t)kk * 64);
            }
        };

        issue(0); cpa_commit();
        issue(1); cpa_commit();

#pragma unroll 1
        for (int kk = 0; kk < 32; kk += 2) {
            cpa_wait<0>();
            __syncthreads();
            if (kk + 2 < 32) {
                issue(kk + 2); cpa_commit();
                issue(kk + 3); cpa_commit();
            }
#pragma unroll
            for (int half = 0; half < 2; half++) {
                const int s = (kk + half) & 3;
                const u32 aBase = aF + (u32)s * ST_SZ;
                const uint4* bst = (const uint4*)(smem + (size_t)s * ST_SZ + ST_B);
                if (ng == 0) {
#pragma unroll
                    for (int sub = 0; sub < 2; sub++) {
                        u32 a0h[4], a0l[4], a1h[4], a1l[4];
                        ldm4(a0h, aBase + sub * 32);
                        ldm4(a0l, aBase + sub * 32 + 10240);
                        ldm4(a1h, aBase + sub * 32 + 20480);
                        ldm4(a1l, aBase + sub * 32 + 30720);
#pragma unroll
                        for (int nt = 0; nt < 4; nt++) {
                            const int bi = (nt * 2 + sub) * 32 + lane;
                            uint4 b0 = bst[bi];
                            uint4 b1 = bst[256 + bi];
                            u32 b0h[2] = {b0.x, b0.y}, b0l[2] = {b0.z, b0.w};
                            u32 b1h[2] = {b1.x, b1.y}, b1l[2] = {b1.z, b1.w};
                            mma_f16(acc[nt], a0h, b0h);
                            mma_f16(acc[nt], a0l, b0h);
                            mma_f16(acc[nt], a0h, b0l);
                            mma_f16(acc[nt], a1h, b1h);
                            mma_f16(acc[nt], a1l, b1h);
                            mma_f16(acc[nt], a1h, b1l);
                        }
                    }
                } else {
#pragma unroll
                    for (int sub = 0; sub < 2; sub++) {
                        u32 a0h[4], a0l[4];
                        ldm4(a0h, aBase + sub * 32);
                        ldm4(a0l, aBase + sub * 32 + 10240);
#pragma unroll
                        for (int nt = 0; nt < 4; nt++) {
                            const int bi = (nt * 2 + sub) * 32 + lane;
                            uint4 b2 = bst[512 + bi];
                            u32 b2h[2] = {b2.x, b2.y}, b2l[2] = {b2.z, b2.w};
                            mma_f16(acc[nt], a0h, b2h);
                            mma_f16(acc[nt], a0l, b2h);
                            mma_f16(acc[nt], a0h, b2l);
                        }
                    }
                }
            }
        }

        if (ng == 0) {
            // ---- L1(t) epilogue ----
            __half* Hhi = g_h1hi[(t + 1) & 1];
            __half* Hlo = g_h1lo[(t + 1) & 1];
#pragma unroll
            for (int rr = 0; rr < 2; rr++) {
                int m = wg * 16 + qr + rr * 8;
                __half hh[2], hl[2];
#pragma unroll
                for (int e = 0; e < 2; e++) {
                    int ri = rr * 2 + e;
                    float iv = acc[0][ri] + bs[0][e];
                    float fv = acc[1][ri] + bs[1][e];
                    float gv = acc[2][ri] + bs[2][e];
                    float ov = acc[3][ri] + bs[3][e];
                    float cn = sigm(fv) * cr[ri] + sigm(iv) * tanhf(gv);
                    cr[ri] = cn;
                    float h = sigm(ov) * tanhf(cn);
                    hh[e] = __float2half_rn(h);
                    hl[e] = __float2half_rn(h - __half2float(hh[e]));
                }
                *(__half2*)&Hhi[m * HID + n0] = __halves2half2(hh[0], hh[1]);
                *(__half2*)&Hlo[m * HID + n0] = __halves2half2(hl[0], hl[1]);
            }
        } else if (do_l0) {
            // ---- L0(t+1) epilogue ----
            const float* xp = g_xproj + (size_t)(t + 1) * BATCH * G4;
            __half* Hhi = g_h0hi[t & 1];
            __half* Hlo = g_h0lo[t & 1];
#pragma unroll
            for (int rr = 0; rr < 2; rr++) {
                int m = wg * 16 + qr + rr * 8;
                const float* xr = xp + (size_t)m * G4 + n0;
                float2 xi = *(const float2*)(xr);
                float2 xf = *(const float2*)(xr + 1024);
                float2 xg = *(const float2*)(xr + 2048);
                float2 xo = *(const float2*)(xr + 3072);
                __half hh[2], hl[2];
#pragma unroll
                for (int e = 0; e < 2; e++) {
                    int ri = rr * 2 + e;
                    float iv = acc[0][ri] + (e ? xi.y : xi.x);
                    float fv = acc[1][ri] + (e ? xf.y : xf.x);
                    float gv = acc[2][ri] + (e ? xg.y : xg.x);
                    float ov = acc[3][ri] + (e ? xo.y : xo.x);
                    float cn = sigm(fv) * cr[ri] + sigm(iv) * tanhf(gv);
                    cr[ri] = cn;
                    float h = sigm(ov) * tanhf(cn);
                    hh[e] = __float2half_rn(h);
                    hl[e] = __float2half_rn(h - __half2float(hh[e]));
                }
                *(__half2*)&Hhi[m * HID + n0] = __halves2half2(hh[0], hh[1]);
                *(__half2*)&Hlo[m * HID + n0] = __halves2half2(hl[0], hl[1]);
            }
        }
        grid_barrier(t + 1);
    }
}

// ===========================================================================
// xproj (round-5 validated, unchanged)
// ===========================================================================
__global__ void __launch_bounds__(256) xproj_kernel(
    const float* __restrict__ xs,
    const float* __restrict__ bih0, const float* __restrict__ bhh0)
{
    __shared__ __align__(16) __half sAhi[2][128][24];
    __shared__ __align__(16) __half sAlo[2][128][24];
    __shared__ uint4 sB[2][8][32];
    const int tid = threadIdx.x;
    const int nbx = blockIdx.x;
    const int mb  = blockIdx.y;
    const int w = tid >> 5, lane = tid & 31, qr = lane >> 2, qc = lane & 3;

    float acc[8][4];
#pragma unroll
    for (int j = 0; j < 8; j++)
#pragma unroll
        for (int k = 0; k < 4; k++) acc[j][k] = 0.f;

    const int srow = tid >> 1, sseg = tid & 1;
    const float* arow = xs + (size_t)(srow * 128 + TOFF + mb) * DIN + sseg * 8;

    float4 rf0, rf1;
    uint4 rb;
    auto ld = [&](int kt) {
        rf0 = *(const float4*)(arow + kt * 16);
        rf1 = *(const float4*)(arow + kt * 16 + 4);
        rb = g_wih0p[((size_t)(nbx * 8 + w) * 32 + kt) * 32 + lane];
    };
    ld(0);
#pragma unroll 1
    for (int kt = 0; kt < 32; kt++) {
        int s = kt & 1;
        __half2* dh = (__half2*)&sAhi[s][srow][sseg * 8];
        __half2* dl = (__half2*)&sAlo[s][srow][sseg * 8];
        float v[8] = {rf0.x, rf0.y, rf0.z, rf0.w, rf1.x, rf1.y, rf1.z, rf1.w};
#pragma unroll
        for (int p = 0; p < 4; p++) {
            float x0 = v[p * 2], x1 = v[p * 2 + 1];
            __half a0 = __float2half_rn(x0), a1 = __float2half_rn(x1);
            dh[p] = __halves2half2(a0, a1);
            dl[p] = __halves2half2(__float2half_rn(x0 - __half2float(a0)),
                                   __float2half_rn(x1 - __half2float(a1)));
        }
        sB[s][w][lane] = rb;
        __syncthreads();
        if (kt + 1 < 32) ld(kt + 1);
        {
            const int r = w * 16 + qr;
            u32 ah[4], al[4];
            ah[0] = *(const u32*)&sAhi[s][r][qc * 2];
            ah[1] = *(const u32*)&sAhi[s][r + 8][qc * 2];
            ah[2] = *(const u32*)&sAhi[s][r][qc * 2 + 8];
            ah[3] = *(const u32*)&sAhi[s][r + 8][qc * 2 + 8];
            al[0] = *(const u32*)&sAlo[s][r][qc * 2];
            al[1] = *(const u32*)&sAlo[s][r + 8][qc * 2];
            al[2] = *(const u32*)&sAlo[s][r][qc * 2 + 8];
            al[3] = *(const u32*)&sAlo[s][r + 8][qc * 2 + 8];
#pragma unroll
            for (int nt = 0; nt < 8; nt++) {
                uint4 bp = sB[s][nt][lane];
                u32 bh[2] = {bp.x, bp.y}, bl[2] = {bp.z, bp.w};
                mma_f16(acc[nt], ah, bh);
                mma_f16(acc[nt], al, bh);
                mma_f16(acc[nt], ah, bl);
            }
        }
        __syncthreads();
    }

    const int m0g = mb * 128 + w * 16 + qr;
#pragma unroll
    for (int nt = 0; nt < 8; nt++) {
        int colb = nbx * 64 + nt * 8 + qc * 2;
        float bv0 = bih0[colb] + bhh0[colb];
        float bv1 = bih0[colb + 1] + bhh0[colb + 1];
        *(float2*)&g_xproj[(size_t)m0g * G4 + colb] =
            make_float2(acc[nt][0] + bv0, acc[nt][1] + bv1);
        *(float2*)&g_xproj[(size_t)(m0g + 8) * G4 + colb] =
            make_float2(acc[nt][2] + bv0, acc[nt][3] + bv1);
    }
}

// ---------------- classifier (unchanged) ------------------------------------
__global__ void __launch_bounds__(256) classifier_kernel(
    const float* __restrict__ Wcls, const float* __restrict__ bcls,
    const float* __restrict__ dropu, float* __restrict__ out)
{
    int gw = (blockIdx.x * blockDim.x + threadIdx.x) >> 5;
    int lane = threadIdx.x & 31;
    int j = gw >> 5;
    int b0 = (gw & 31) * 4;
    const __half* hi = g_h1hi[0];
    const __half* lo = g_h1lo[0];

    float acc[4] = {0.f, 0.f, 0.f, 0.f};
#pragma unroll
    for (int it = 0; it < 8; ++it) {
        int h = it * 128 + lane * 4;
        float4 wv = *(const float4*)&Wcls[(size_t)j * HID + h];
#pragma unroll
        for (int bi = 0; bi < 4; ++bi) {
            int b = b0 + bi;
            int idx = b * HID + h;
            __half2 a0 = *(const __half2*)&hi[idx];
            __half2 a1 = *(const __half2*)&hi[idx + 2];
            __half2 c0 = *(const __half2*)&lo[idx];
            __half2 c1 = *(const __half2*)&lo[idx + 2];
            float2 f0 = __half22float2(a0), f1 = __half22float2(a1);
            float2 g0 = __half22float2(c0), g1 = __half22float2(c1);
            float x0 = f0.x + g0.x, x1 = f0.y + g0.y;
            float x2 = f1.x + g1.x, x3 = f1.y + g1.y;
            float4 u = *(const float4*)&dropu[(size_t)b * HID + h];
            acc[bi] += (u.x > 0.5f ? x0 : 0.f) * wv.x
                     + (u.y > 0.5f ? x1 : 0.f) * wv.y
                     + (u.z > 0.5f ? x2 : 0.f) * wv.z
                     + (u.w > 0.5f ? x3 : 0.f) * wv.w;
        }
    }
#pragma unroll
    for (int bi = 0; bi < 4; ++bi) {
        float v = acc[bi];
#pragma unroll
        for (int off = 16; off; off >>= 1)
            v += __shfl_xor_sync(0xffffffffu, v, off);
        if (lane == 0)
            out[(size_t)(b0 + bi) * 1000 + j] = 2.0f * v + bcls[j];
    }
}

// ---------------- launch ----------------------------------------------------
extern "C" void kernel_launch(void* const* d_in, const int* in_sizes, int n_in,
                              void* d_out, int out_size)
{
    const float* xs    = (const float*)d_in[0];
    const float* Wih0  = (const float*)d_in[1];
    const float* Whh0  = (const float*)d_in[2];
    const float* bih0  = (const float*)d_in[3];
    const float* bhh0  = (const float*)d_in[4];
    const float* Wih1  = (const float*)d_in[5];
    const float* Whh1  = (const float*)d_in[6];
    const float* bih1  = (const float*)d_in[7];
    const float* bhh1  = (const float*)d_in[8];
    const float* Wcls  = (const float*)d_in[9];
    const float* bcls  = (const float*)d_in[10];
    const float* dropu = (const float*)d_in[11];
    float* out = (float*)d_out;

    cudaFuncSetAttribute(step_persist, cudaFuncAttributeMaxDynamicSharedMemorySize, PS_TOTAL);

    init_states<<<(BATCH * HID + 255) / 256, 256>>>();
    pack_all<<<(3 * PACK_N64 + PACK_N32) / 256, 256>>>(Whh0, Wih1, Whh1, Wih0);
    xproj_kernel<<<dim3(64, 64), 256>>>(xs, bih0, bhh0);
    step_persist<<<128, 512, PS_TOTAL>>>(bih1, bhh1);
    classifier_kernel<<<4000, 256>>>(Wcls, bcls, dropu, out);
}

// round 10
// speedup vs baseline: 1.3287x; 1.0202x over previous
#include <cuda_runtime.h>
#include <cuda_fp16.h>

#define BATCH 128
#define DIN   512
#define HID   1024
#define G4    4096
#define STEPS 64
#define TOFF  55   // (128 - 64 - 9)

typedef unsigned int u32;

// ---------------- device scratch (no allocations allowed) -----------------
__device__ float  g_xproj[(size_t)STEPS * BATCH * G4];
__device__ __half g_h0hi[2][BATCH * HID], g_h0lo[2][BATCH * HID];
__device__ __half g_h1hi[2][BATCH * HID], g_h1lo[2][BATCH * HID];
__device__ float  g_c0[BATCH * HID];
__device__ uint4  g_whh0p[(size_t)512 * 64 * 32];
__device__ uint4  g_wih1p[(size_t)512 * 64 * 32];
__device__ uint4  g_whh1p[(size_t)512 * 64 * 32];
__device__ uint4  g_wih0p[(size_t)512 * 32 * 32];
__device__ u32    g_bar_count, g_bar_gen;

__device__ __forceinline__ float sigm(float x) { return 1.0f / (1.0f + expf(-x)); }
__device__ __forceinline__ u32 h2u(__half2 h) { return *(u32*)&h; }

__device__ __forceinline__ void mma_f16(float* d, const u32* a, const u32* b) {
    asm volatile("mma.sync.aligned.m16n8k16.row.col.f32.f16.f16.f32 "
        "{%0,%1,%2,%3},{%4,%5,%6,%7},{%8,%9},{%0,%1,%2,%3};"
        : "+f"(d[0]), "+f"(d[1]), "+f"(d[2]), "+f"(d[3])
        : "r"(a[0]), "r"(a[1]), "r"(a[2]), "r"(a[3]), "r"(b[0]), "r"(b[1]));
}
__device__ __forceinline__ u32 smem_u32(const void* p) {
    u32 a;
    asm("{ .reg .u64 t; cvta.to.shared.u64 t, %1; cvt.u32.u64 %0, t; }" : "=r"(a) : "l"(p));
    return a;
}
__device__ __forceinline__ void cpa16(u32 dst, const void* src) {
    asm volatile("cp.async.cg.shared.global [%0], [%1], 16;"
                 :: "r"(dst), "l"(__cvta_generic_to_global(src)) : "memory");
}
__device__ __forceinline__ void cpa_commit() {
    asm volatile("cp.async.commit_group;" ::: "memory");
}
template<int N> __device__ __forceinline__ void cpa_wait() {
    asm volatile("cp.async.wait_group %0;" :: "n"(N) : "memory");
}
__device__ __forceinline__ void ldm4(u32* r, u32 addr) {
    asm volatile("ldmatrix.sync.aligned.m8n8.x4.shared.b16 {%0,%1,%2,%3}, [%4];"
        : "=r"(r[0]), "=r"(r[1]), "=r"(r[2]), "=r"(r[3]) : "r"(addr));
}

// smem stage layout (53248 B per stage, 4 stages = 212992 B):
//  +0      A0hi (10240 = 128 rows x 80B, 64B data = K32)
//  +10240  A0lo   +20480  A1hi   +30720  A1lo
//  +40960  B: mat0(wih1) 4096 | mat1(whh1) 4096 | mat2(whh0) 4096
#define ST_SZ    53248
#define ST_B     40960
#define PS_TOTAL (4 * ST_SZ)

// ---------------- grid-wide software barrier (128 CTAs) --------------------
__device__ __forceinline__ void grid_barrier(int gen) {
    __syncthreads();
    if (threadIdx.x == 0) {
        __threadfence();
        u32 prev = atomicAdd(&g_bar_count, 1u);
        if (prev == (u32)(gen * 128 + 127)) {
            atomicExch(&g_bar_gen, (u32)(gen + 1));
        } else {
            u32 g;
            do {
                __nanosleep(64);
                asm volatile("ld.acquire.gpu.u32 %0, [%1];"
                             : "=r"(g) : "l"((const u32*)&g_bar_gen));
            } while (g <= (u32)gen);
        }
    }
    __syncthreads();
}

// ---------------- init states ----------------------------------------------
__global__ void init_states() {
    int i = blockIdx.x * blockDim.x + threadIdx.x;
    if (i == 0) { g_bar_count = 0u; g_bar_gen = 0u; }
    if (i < BATCH * HID) {
        __half z = __float2half(0.f);
        g_h0hi[0][i] = z; g_h0lo[0][i] = z; g_h0hi[1][i] = z; g_h0lo[1][i] = z;
        g_h1hi[0][i] = z; g_h1lo[0][i] = z; g_h1hi[1][i] = z; g_h1lo[1][i] = z;
        g_c0[i] = 0.f;
    }
}

// ---------------- weight packer (single launch) ----------------------------
__device__ __forceinline__ void pack_one(
    const float* __restrict__ W, uint4* __restrict__ dst, int Kt, int idx)
{
    int lane = idx & 31;
    int rest = idx >> 5;
    int kt = rest % Kt, nt = rest / Kt;
    int K = Kt * 16;
    int n = nt * 8 + (lane >> 2);
    int k0 = kt * 16 + (lane & 3) * 2;
    const float* wr = W + (size_t)n * K + k0;
    float w00 = wr[0], w01 = wr[1], w10 = wr[8], w11 = wr[9];
    __half h00 = __float2half_rn(w00), h01 = __float2half_rn(w01);
    __half h10 = __float2half_rn(w10), h11 = __float2half_rn(w11);
    uint4 v;
    v.x = h2u(__halves2half2(h00, h01));
    v.y = h2u(__halves2half2(h10, h11));
    v.z = h2u(__halves2half2(__float2half_rn(w00 - __half2float(h00)),
                             __float2half_rn(w01 - __half2float(h01))));
    v.w = h2u(__halves2half2(__float2half_rn(w10 - __half2float(h10)),
                             __float2half_rn(w11 - __half2float(h11))));
    dst[idx] = v;
}
#define PACK_N64 (512 * 64 * 32)
#define PACK_N32 (512 * 32 * 32)
__global__ void pack_all(const float* __restrict__ Whh0, const float* __restrict__ Wih1,
                         const float* __restrict__ Whh1, const float* __restrict__ Wih0) {
    int idx = blockIdx.x * 256 + threadIdx.x;
    if (idx < PACK_N64)               pack_one(Whh0, g_whh0p, 64, idx);
    else if (idx < 2 * PACK_N64)      pack_one(Wih1, g_wih1p, 64, idx - PACK_N64);
    else if (idx < 3 * PACK_N64)      pack_one(Whh1, g_whh1p, 64, idx - 2 * PACK_N64);
    else                              pack_one(Wih0, g_wih0p, 32, idx - 3 * PACK_N64);
}

// ===========================================================================
// Persistent fused-step kernel. Grid 128, 768 threads = 24 warps.
// wg = w&7 -> mtile (rows wg*16..+15); job = w>>3:
//   job0: h0(t+1)@Wih1 -> acc (L1 part a)   24 MMA/chunk
//   job1: h1(t)  @Whh1 -> acc (L1 part b)   24 MMA/chunk  -> smem partials
//   job2: h0(t+1)@Whh0 -> acc (L0)          24 MMA/chunk
// Perfectly balanced 6 warps/SMSP. One 16KB partial-combine per step.
// Epilogues: job0 -> L1(t) cell (c1+biases in regs, adds job1 partials);
//            job2 -> L0(t+1) cell (c0 in regs).
// ===========================================================================
__global__ void __launch_bounds__(768) step_persist(
    const float* __restrict__ bih1, const float* __restrict__ bhh1)
{
    extern __shared__ char smem[];
    const int tid = threadIdx.x, bx = blockIdx.x;
    const int w = tid >> 5, lane = tid & 31, qr = lane >> 2, qc = lane & 3;
    const int wg = w & 7, job = w >> 3;
    const u32 sb = smem_u32(smem);
    const int n0 = bx * 8 + qc * 2;

    // ---- prologue: L0 step 0 (h0 = 0) on this CTA's 8 columns ----
    for (int i = tid; i < 128 * 8; i += 768) {
        int m = i >> 3, u = i & 7;
        int n = bx * 8 + u;
        const float* xr = g_xproj + (size_t)m * G4;
        float iv = xr[n], gv = xr[2048 + n], ov = xr[3072 + n];
        float cn = sigm(iv) * tanhf(gv);
        g_c0[m * HID + n] = cn;
        float h = sigm(ov) * tanhf(cn);
        __half hh = __float2half_rn(h);
        g_h0hi[1][m * HID + n] = hh;
        g_h0lo[1][m * HID + n] = __float2half_rn(h - __half2float(hh));
    }
    grid_barrier(0);

    // biases (L1) in regs (job0 only uses them)
    float bs[4][2];
#pragma unroll
    for (int g = 0; g < 4; g++) {
        bs[g][0] = bih1[g * 1024 + n0] + bhh1[g * 1024 + n0];
        bs[g][1] = bih1[g * 1024 + n0 + 1] + bhh1[g * 1024 + n0 + 1];
    }
    // c-state in regs: job0 -> c1 (zeros), job2 -> c0 (from prologue)
    float cr[4] = {0.f, 0.f, 0.f, 0.f};
    if (job == 2) {
#pragma unroll
        for (int rr = 0; rr < 2; rr++) {
            int m = wg * 16 + qr + rr * 8;
            cr[rr * 2 + 0] = g_c0[m * HID + n0];
            cr[rr * 2 + 1] = g_c0[m * HID + n0 + 1];
        }
    }

    // ---- invariant staging coords ----
    // A: threads 0..511 do 4 cp16 each (2048 cps = 4 planes x 128 rows x 4 segs)
    u32 adst[4]; u32 arow[4]; int aplane[4]; int aseg[4];
#pragma unroll
    for (int i = 0; i < 4; i++) {
        int idx = (tid & 511) + i * 512;
        aplane[i] = idx >> 9;
        arow[i] = (idx >> 2) & 127;
        aseg[i] = idx & 3;
        adst[i] = sb + aplane[i] * 10240 + arow[i] * 80 + aseg[i] * 16;
    }
    const bool doA = (tid < 512);
    // B: threads 512..767 do 3 cp16 (one per matrix)
    const bool doB = (tid >= 512);
    const int btl = tid & 255;
    const int tw = btl >> 5;
    const u32 bdst0 = sb + ST_B + (btl << 4);
    const size_t bsrc0 = (((size_t)((tw >> 1) * 128 + bx)) * 64 + (tw & 1)) * 32 + lane;
    // A fragment base (ldmatrix) for this warp's mtile + job's A source
    const u32 jobAoff = (job == 1) ? 20480u : 0u;
    const u32 aF = sb + jobAoff + (wg * 16 + (lane & 15)) * 80 + ((lane >> 4) * 16);
    // B matrix offset within stage (uint4 index): job0->wih1, job1->whh1, job2->whh0
    const int bmat = job * 256;

    float* red = (float*)smem;   // 16KB partial buffer (reuses stage 0 A area)

#pragma unroll 1
    for (int t = 0; t < STEPS; t++) {
        const int do_l0 = (t < STEPS - 1);
        const __half* Ap0 = g_h0hi[(t + 1) & 1];   // plane 0
        const __half* Ap1 = g_h0lo[(t + 1) & 1];   // plane 1
        const __half* Ap2 = g_h1hi[t & 1];         // plane 2
        const __half* Ap3 = g_h1lo[t & 1];         // plane 3

        float acc[4][4];
#pragma unroll
        for (int j = 0; j < 4; j++)
#pragma unroll
            for (int k = 0; k < 4; k++) acc[j][k] = 0.f;

        auto issue = [&](int kk) {
            const u32 soff = (u32)(kk & 3) * ST_SZ;
            if (doA) {
#pragma unroll
                for (int i = 0; i < 4; i++) {
                    const __half* base = (aplane[i] == 0) ? Ap0 :
                                         (aplane[i] == 1) ? Ap1 :
                                         (aplane[i] == 2) ? Ap2 : Ap3;
                    cpa16(adst[i] + soff,
                          base + (size_t)arow[i] * HID + kk * 32 + aseg[i] * 8);
                }
            } else {
                cpa16(bdst0 + soff,        g_wih1p + bsrc0 + (size_t)kk * 64);
                cpa16(bdst0 + soff + 4096, g_whh1p + bsrc0 + (size_t)kk * 64);
                cpa16(bdst0 + soff + 8192, g_whh0p + bsrc0 + (size_t)kk * 64);
            }
        };

        issue(0); cpa_commit();
        issue(1); cpa_commit();

#pragma unroll 1
        for (int kk = 0; kk < 32; kk += 2) {
            cpa_wait<0>();
            __syncthreads();
            if (kk + 2 < 32) {
                issue(kk + 2); cpa_commit();
                issue(kk + 3); cpa_commit();
            }
#pragma unroll
            for (int half = 0; half < 2; half++) {
                const int s = (kk + half) & 3;
                const u32 aBase = aF + (u32)s * ST_SZ;
                const uint4* bst = (const uint4*)(smem + (size_t)s * ST_SZ + ST_B);
#pragma unroll
                for (int sub = 0; sub < 2; sub++) {
                    u32 ah[4], al[4];
                    ldm4(ah, aBase + sub * 32);
                    ldm4(al, aBase + sub * 32 + 10240);
#pragma unroll
                    for (int nt = 0; nt < 4; nt++) {
                        uint4 bp = bst[bmat + (nt * 2 + sub) * 32 + lane];
                        u32 bh[2] = {bp.x, bp.y}, bl[2] = {bp.z, bp.w};
                        mma_f16(acc[nt], ah, bh);
                        mma_f16(acc[nt], al, bh);
                        mma_f16(acc[nt], ah, bl);
                    }
                }
            }
        }
        cpa_wait<0>();

        // ---- combine: job1 publishes L1 partials ----
        __syncthreads();
        if (job == 1) {
#pragma unroll
            for (int nt = 0; nt < 4; nt++)
#pragma unroll
                for (int r = 0; r < 4; r++)
                    red[(((wg * 4 + nt) * 4 + r) << 5) + lane] = acc[nt][r];
        }
        __syncthreads();

        if (job == 0) {
            // ---- L1(t) epilogue ----
            __half* Hhi = g_h1hi[(t + 1) & 1];
            __half* Hlo = g_h1lo[(t + 1) & 1];
#pragma unroll
            for (int rr = 0; rr < 2; rr++) {
                int m = wg * 16 + qr + rr * 8;
                __half hh[2], hl[2];
#pragma unroll
                for (int e = 0; e < 2; e++) {
                    int ri = rr * 2 + e;
                    float pI = red[(((wg * 4 + 0) * 4 + ri) << 5) + lane];
                    float pF = red[(((wg * 4 + 1) * 4 + ri) << 5) + lane];
                    float pG = red[(((wg * 4 + 2) * 4 + ri) << 5) + lane];
                    float pO = red[(((wg * 4 + 3) * 4 + ri) << 5) + lane];
                    float iv = acc[0][ri] + pI + bs[0][e];
                    float fv = acc[1][ri] + pF + bs[1][e];
                    float gv = acc[2][ri] + pG + bs[2][e];
                    float ov = acc[3][ri] + pO + bs[3][e];
                    float cn = sigm(fv) * cr[ri] + sigm(iv) * tanhf(gv);
                    cr[ri] = cn;
                    float h = sigm(ov) * tanhf(cn);
                    hh[e] = __float2half_rn(h);
                    hl[e] = __float2half_rn(h - __half2float(hh[e]));
                }
                *(__half2*)&Hhi[m * HID + n0] = __halves2half2(hh[0], hh[1]);
                *(__half2*)&Hlo[m * HID + n0] = __halves2half2(hl[0], hl[1]);
            }
        } else if (job == 2 && do_l0) {
            // ---- L0(t+1) epilogue ----
            const float* xp = g_xproj + (size_t)(t + 1) * BATCH * G4;
            __half* Hhi = g_h0hi[t & 1];
            __half* Hlo = g_h0lo[t & 1];
#pragma unroll
            for (int rr = 0; rr < 2; rr++) {
                int m = wg * 16 + qr + rr * 8;
                const float* xr = xp + (size_t)m * G4 + n0;
                float2 xi = *(const float2*)(xr);
                float2 xf = *(const float2*)(xr + 1024);
                float2 xg = *(const float2*)(xr + 2048);
                float2 xo = *(const float2*)(xr + 3072);
                __half hh[2], hl[2];
#pragma unroll
                for (int e = 0; e < 2; e++) {
                    int ri = rr * 2 + e;
                    float iv = acc[0][ri] + (e ? xi.y : xi.x);
                    float fv = acc[1][ri] + (e ? xf.y : xf.x);
                    float gv = acc[2][ri] + (e ? xg.y : xg.x);
                    float ov = acc[3][ri] + (e ? xo.y : xo.x);
                    float cn = sigm(fv) * cr[ri] + sigm(iv) * tanhf(gv);
                    cr[ri] = cn;
                    float h = sigm(ov) * tanhf(cn);
                    hh[e] = __float2half_rn(h);
                    hl[e] = __float2half_rn(h - __half2float(hh[e]));
                }
                *(__half2*)&Hhi[m * HID + n0] = __halves2half2(hh[0], hh[1]);
                *(__half2*)&Hlo[m * HID + n0] = __halves2half2(hl[0], hl[1]);
            }
        }
        grid_barrier(t + 1);
    }
}

// ===========================================================================
// xproj (round-5 validated, unchanged)
// ===========================================================================
__global__ void __launch_bounds__(256) xproj_kernel(
    const float* __restrict__ xs,
    const float* __restrict__ bih0, const float* __restrict__ bhh0)
{
    __shared__ __align__(16) __half sAhi[2][128][24];
    __shared__ __align__(16) __half sAlo[2][128][24];
    __shared__ uint4 sB[2][8][32];
    const int tid = threadIdx.x;
    const int nbx = blockIdx.x;
    const int mb  = blockIdx.y;
    const int w = tid >> 5, lane = tid & 31, qr = lane >> 2, qc = lane & 3;

    float acc[8][4];
#pragma unroll
    for (int j = 0; j < 8; j++)
#pragma unroll
        for (int k = 0; k < 4; k++) acc[j][k] = 0.f;

    const int srow = tid >> 1, sseg = tid & 1;
    const float* arow = xs + (size_t)(srow * 128 + TOFF + mb) * DIN + sseg * 8;

    float4 rf0, rf1;
    uint4 rb;
    auto ld = [&](int kt) {
        rf0 = *(const float4*)(arow + kt * 16);
        rf1 = *(const float4*)(arow + kt * 16 + 4);
        rb = g_wih0p[((size_t)(nbx * 8 + w) * 32 + kt) * 32 + lane];
    };
    ld(0);
#pragma unroll 1
    for (int kt = 0; kt < 32; kt++) {
        int s = kt & 1;
        __half2* dh = (__half2*)&sAhi[s][srow][sseg * 8];
        __half2* dl = (__half2*)&sAlo[s][srow][sseg * 8];
        float v[8] = {rf0.x, rf0.y, rf0.z, rf0.w, rf1.x, rf1.y, rf1.z, rf1.w};
#pragma unroll
        for (int p = 0; p < 4; p++) {
            float x0 = v[p * 2], x1 = v[p * 2 + 1];
            __half a0 = __float2half_rn(x0), a1 = __float2half_rn(x1);
            dh[p] = __halves2half2(a0, a1);
            dl[p] = __halves2half2(__float2half_rn(x0 - __half2float(a0)),
                                   __float2half_rn(x1 - __half2float(a1)));
        }
        sB[s][w][lane] = rb;
        __syncthreads();
        if (kt + 1 < 32) ld(kt + 1);
        {
            const int r = w * 16 + qr;
            u32 ah[4], al[4];
            ah[0] = *(const u32*)&sAhi[s][r][qc * 2];
            ah[1] = *(const u32*)&sAhi[s][r + 8][qc * 2];
            ah[2] = *(const u32*)&sAhi[s][r][qc * 2 + 8];
            ah[3] = *(const u32*)&sAhi[s][r + 8][qc * 2 + 8];
            al[0] = *(const u32*)&sAlo[s][r][qc * 2];
            al[1] = *(const u32*)&sAlo[s][r + 8][qc * 2];
            al[2] = *(const u32*)&sAlo[s][r][qc * 2 + 8];
            al[3] = *(const u32*)&sAlo[s][r + 8][qc * 2 + 8];
#pragma unroll
            for (int nt = 0; nt < 8; nt++) {
                uint4 bp = sB[s][nt][lane];
                u32 bh[2] = {bp.x, bp.y}, bl[2] = {bp.z, bp.w};
                mma_f16(acc[nt], ah, bh);
                mma_f16(acc[nt], al, bh);
                mma_f16(acc[nt], ah, bl);
            }
        }
        __syncthreads();
    }

    const int m0g = mb * 128 + w * 16 + qr;
#pragma unroll
    for (int nt = 0; nt < 8; nt++) {
        int colb = nbx * 64 + nt * 8 + qc * 2;
        float bv0 = bih0[colb] + bhh0[colb];
        float bv1 = bih0[colb + 1] + bhh0[colb + 1];
        *(float2*)&g_xproj[(size_t)m0g * G4 + colb] =
            make_float2(acc[nt][0] + bv0, acc[nt][1] + bv1);
        *(float2*)&g_xproj[(size_t)(m0g + 8) * G4 + colb] =
            make_float2(acc[nt][2] + bv0, acc[nt][3] + bv1);
    }
}

// ---------------- classifier (unchanged) ------------------------------------
__global__ void __launch_bounds__(256) classifier_kernel(
    const float* __restrict__ Wcls, const float* __restrict__ bcls,
    const float* __restrict__ dropu, float* __restrict__ out)
{
    int gw = (blockIdx.x * blockDim.x + threadIdx.x) >> 5;
    int lane = threadIdx.x & 31;
    int j = gw >> 5;
    int b0 = (gw & 31) * 4;
    const __half* hi = g_h1hi[0];
    const __half* lo = g_h1lo[0];

    float acc[4] = {0.f, 0.f, 0.f, 0.f};
#pragma unroll
    for (int it = 0; it < 8; ++it) {
        int h = it * 128 + lane * 4;
        float4 wv = *(const float4*)&Wcls[(size_t)j * HID + h];
#pragma unroll
        for (int bi = 0; bi < 4; ++bi) {
            int b = b0 + bi;
            int idx = b * HID + h;
            __half2 a0 = *(const __half2*)&hi[idx];
            __half2 a1 = *(const __half2*)&hi[idx + 2];
            __half2 c0 = *(const __half2*)&lo[idx];
            __half2 c1 = *(const __half2*)&lo[idx + 2];
            float2 f0 = __half22float2(a0), f1 = __half22float2(a1);
            float2 g0 = __half22float2(c0), g1 = __half22float2(c1);
            float x0 = f0.x + g0.x, x1 = f0.y + g0.y;
            float x2 = f1.x + g1.x, x3 = f1.y + g1.y;
            float4 u = *(const float4*)&dropu[(size_t)b * HID + h];
            acc[bi] += (u.x > 0.5f ? x0 : 0.f) * wv.x
                     + (u.y > 0.5f ? x1 : 0.f) * wv.y
                     + (u.z > 0.5f ? x2 : 0.f) * wv.z
                     + (u.w > 0.5f ? x3 : 0.f) * wv.w;
        }
    }
#pragma unroll
    for (int bi = 0; bi < 4; ++bi) {
        float v = acc[bi];
#pragma unroll
        for (int off = 16; off; off >>= 1)
            v += __shfl_xor_sync(0xffffffffu, v, off);
        if (lane == 0)
            out[(size_t)(b0 + bi) * 1000 + j] = 2.0f * v + bcls[j];
    }
}

// ---------------- launch ----------------------------------------------------
extern "C" void kernel_launch(void* const* d_in, const int* in_sizes, int n_in,
                              void* d_out, int out_size)
{
    const float* xs    = (const float*)d_in[0];
    const float* Wih0  = (const float*)d_in[1];
    const float* Whh0  = (const float*)d_in[2];
    const float* bih0  = (const float*)d_in[3];
    const float* bhh0  = (const float*)d_in[4];
    const float* Wih1  = (const float*)d_in[5];
    const float* Whh1  = (const float*)d_in[6];
    const float* bih1  = (const float*)d_in[7];
    const float* bhh1  = (const float*)d_in[8];
    const float* Wcls  = (const float*)d_in[9];
    const float* bcls  = (const float*)d_in[10];
    const float* dropu = (const float*)d_in[11];
    float* out = (float*)d_out;

    cudaFuncSetAttribute(step_persist, cudaFuncAttributeMaxDynamicSharedMemorySize, PS_TOTAL);

    init_states<<<(BATCH * HID + 255) / 256, 256>>>();
    pack_all<<<(3 * PACK_N64 + PACK_N32) / 256, 256>>>(Whh0, Wih1, Whh1, Wih0);
    xproj_kernel<<<dim3(64, 64), 256>>>(xs, bih0, bhh0);
    step_persist<<<128, 768, PS_TOTAL>>>(bih1, bhh1);
    classifier_kernel<<<4000, 256>>>(Wcls, bcls, dropu, out);
}

// round 11
// speedup vs baseline: 1.4221x; 1.0703x over previous
#include <cuda_runtime.h>
#include <cuda_fp16.h>

#define BATCH 128
#define DIN   512
#define HID   1024
#define G4    4096
#define STEPS 64
#define TOFF  55   // (128 - 64 - 9)

typedef unsigned int u32;

// ---------------- device scratch (no allocations allowed) -----------------
__device__ float  g_xproj[(size_t)STEPS * BATCH * G4];
__device__ __half g_h0hi[2][BATCH * HID], g_h0lo[2][BATCH * HID];
__device__ __half g_h1hi[2][BATCH * HID], g_h1lo[2][BATCH * HID];
__device__ float  g_c0[BATCH * HID];
__device__ __half g_xshi[(size_t)STEPS * BATCH * DIN];   // xs split, [t][b][k]
__device__ __half g_xslo[(size_t)STEPS * BATCH * DIN];
__device__ uint4  g_whh0p[(size_t)512 * 64 * 32];
__device__ uint4  g_wih1p[(size_t)512 * 64 * 32];
__device__ uint4  g_whh1p[(size_t)512 * 64 * 32];
__device__ uint4  g_wih0p[(size_t)512 * 32 * 32];
__device__ u32    g_bar_count, g_bar_gen;

__device__ __forceinline__ float sigm(float x) { return 1.0f / (1.0f + expf(-x)); }
__device__ __forceinline__ u32 h2u(__half2 h) { return *(u32*)&h; }

__device__ __forceinline__ void mma_f16(float* d, const u32* a, const u32* b) {
    asm volatile("mma.sync.aligned.m16n8k16.row.col.f32.f16.f16.f32 "
        "{%0,%1,%2,%3},{%4,%5,%6,%7},{%8,%9},{%0,%1,%2,%3};"
        : "+f"(d[0]), "+f"(d[1]), "+f"(d[2]), "+f"(d[3])
        : "r"(a[0]), "r"(a[1]), "r"(a[2]), "r"(a[3]), "r"(b[0]), "r"(b[1]));
}
__device__ __forceinline__ u32 smem_u32(const void* p) {
    u32 a;
    asm("{ .reg .u64 t; cvta.to.shared.u64 t, %1; cvt.u32.u64 %0, t; }" : "=r"(a) : "l"(p));
    return a;
}
__device__ __forceinline__ void cpa16(u32 dst, const void* src) {
    asm volatile("cp.async.cg.shared.global [%0], [%1], 16;"
                 :: "r"(dst), "l"(__cvta_generic_to_global(src)) : "memory");
}
__device__ __forceinline__ void cpa_commit() {
    asm volatile("cp.async.commit_group;" ::: "memory");
}
template<int N> __device__ __forceinline__ void cpa_wait() {
    asm volatile("cp.async.wait_group %0;" :: "n"(N) : "memory");
}
__device__ __forceinline__ void ldm4(u32* r, u32 addr) {
    asm volatile("ldmatrix.sync.aligned.m8n8.x4.shared.b16 {%0,%1,%2,%3}, [%4];"
        : "=r"(r[0]), "=r"(r[1]), "=r"(r[2]), "=r"(r[3]) : "r"(addr));
}

// step-kernel smem: 4 stages of 53248 B
#define ST_SZ    53248
#define ST_B     40960
#define PS_TOTAL (4 * ST_SZ)

// xproj smem: 4 stages of 36864 B (Ahi 10240 | Alo 10240 | B 16384)
#define XP_ST    36864
#define XP_B     20480
#define XP_TOTAL (4 * XP_ST)

// ---------------- grid-wide software barrier (128 CTAs) --------------------
__device__ __forceinline__ void grid_barrier(int gen) {
    __syncthreads();
    if (threadIdx.x == 0) {
        __threadfence();
        u32 prev = atomicAdd(&g_bar_count, 1u);
        if (prev == (u32)(gen * 128 + 127)) {
            atomicExch(&g_bar_gen, (u32)(gen + 1));
        } else {
            u32 g;
            do {
                __nanosleep(64);
                asm volatile("ld.acquire.gpu.u32 %0, [%1];"
                             : "=r"(g) : "l"((const u32*)&g_bar_gen));
            } while (g <= (u32)gen);
        }
    }
    __syncthreads();
}

// ---------------- init states ----------------------------------------------
__global__ void init_states() {
    int i = blockIdx.x * blockDim.x + threadIdx.x;
    if (i == 0) { g_bar_count = 0u; g_bar_gen = 0u; }
    if (i < BATCH * HID) {
        __half z = __float2half(0.f);
        g_h0hi[0][i] = z; g_h0lo[0][i] = z; g_h0hi[1][i] = z; g_h0lo[1][i] = z;
        g_h1hi[0][i] = z; g_h1lo[0][i] = z; g_h1hi[1][i] = z; g_h1lo[1][i] = z;
        g_c0[i] = 0.f;
    }
}

// ---------------- packers (single launch) ----------------------------------
__device__ __forceinline__ void pack_one(
    const float* __restrict__ W, uint4* __restrict__ dst, int Kt, int idx)
{
    int lane = idx & 31;
    int rest = idx >> 5;
    int kt = rest % Kt, nt = rest / Kt;
    int K = Kt * 16;
    int n = nt * 8 + (lane >> 2);
    int k0 = kt * 16 + (lane & 3) * 2;
    const float* wr = W + (size_t)n * K + k0;
    float w00 = wr[0], w01 = wr[1], w10 = wr[8], w11 = wr[9];
    __half h00 = __float2half_rn(w00), h01 = __float2half_rn(w01);
    __half h10 = __float2half_rn(w10), h11 = __float2half_rn(w11);
    uint4 v;
    v.x = h2u(__halves2half2(h00, h01));
    v.y = h2u(__halves2half2(h10, h11));
    v.z = h2u(__halves2half2(__float2half_rn(w00 - __half2float(h00)),
                             __float2half_rn(w01 - __half2float(h01))));
    v.w = h2u(__halves2half2(__float2half_rn(w10 - __half2float(h10)),
                             __float2half_rn(w11 - __half2float(h11))));
    dst[idx] = v;
}
__device__ __forceinline__ void pack_xs_one(const float* __restrict__ xs, int idx) {
    int k = idx & 511;
    int b = (idx >> 9) & 127;
    int t = idx >> 16;
    float x = xs[((size_t)(b * 128 + TOFF + t)) * DIN + k];
    __half h = __float2half_rn(x);
    g_xshi[idx] = h;
    g_xslo[idx] = __float2half_rn(x - __half2float(h));
}
#define PACK_N64 (512 * 64 * 32)
#define PACK_N32 (512 * 32 * 32)
#define PACK_XS  (STEPS * BATCH * DIN)
#define PACK_TOTAL (3 * PACK_N64 + PACK_N32 + PACK_XS)
__global__ void pack_all(const float* __restrict__ Whh0, const float* __restrict__ Wih1,
                         const float* __restrict__ Whh1, const float* __restrict__ Wih0,
                         const float* __restrict__ xs) {
    int idx = blockIdx.x * 256 + threadIdx.x;
    if (idx < PACK_N64)                          pack_one(Whh0, g_whh0p, 64, idx);
    else if (idx < 2 * PACK_N64)                 pack_one(Wih1, g_wih1p, 64, idx - PACK_N64);
    else if (idx < 3 * PACK_N64)                 pack_one(Whh1, g_whh1p, 64, idx - 2 * PACK_N64);
    else if (idx < 3 * PACK_N64 + PACK_N32)      pack_one(Wih0, g_wih0p, 32, idx - 3 * PACK_N64);
    else                                         pack_xs_one(xs, idx - 3 * PACK_N64 - PACK_N32);
}

// ===========================================================================
// xproj v3: D[8192,4096] = xs_split @ Wih0^T + biases.
// Grid (32 colblocks, 64 times), 512 threads = 16 warps.
// Warp = 2 mtiles x 4 ntiles (wg2 = w&3 -> mt pair, nq = w>>2 -> nt quad).
// 4-stage cp.async, 16 K32-chunks, sync every 2 chunks.
// ===========================================================================
__global__ void __launch_bounds__(512) xproj_kernel(
    const float* __restrict__ bih0, const float* __restrict__ bhh0)
{
    extern __shared__ char smem[];
    const int tid = threadIdx.x;
    const int nbx = blockIdx.x;   // 128-col block
    const int mb  = blockIdx.y;   // time index
    const int w = tid >> 5, lane = tid & 31, qr = lane >> 2, qc = lane & 3;
    const int wg2 = w & 3, nq = w >> 2;
    const u32 sb = smem_u32(smem);

    float acc[2][4][4];
#pragma unroll
    for (int i = 0; i < 2; i++)
#pragma unroll
        for (int j = 0; j < 4; j++)
#pragma unroll
            for (int k = 0; k < 4; k++) acc[i][j][k] = 0.f;

    const bool doA = (tid < 256);
    // A staging: threads 0..255, 4 cp16 each (2 planes x 128 rows x 4 segs)
    u32 adst[4]; const __half* asrc[4];
#pragma unroll
    for (int i = 0; i < 4; i++) {
        int idx = (tid & 255) + i * 256;
        int plane = idx >> 9, row = (idx >> 2) & 127, seg = idx & 3;
        adst[i] = sb + plane * 10240 + row * 80 + seg * 16;
        const __half* base = plane ? g_xslo : g_xshi;
        asrc[i] = base + (size_t)(mb * 128 + row) * DIN + seg * 8;
    }
    // B staging: threads 256..511, 4 cp16 each (32 frags x 32 lanes)
    u32 bdst[4]; size_t bsrc[4];
#pragma unroll
    for (int i = 0; i < 4; i++) {
        int idx = (tid & 255) + i * 256;
        int f = idx >> 5, ln = idx & 31;           // f: nt*2+sub
        bdst[i] = sb + XP_B + ((u32)idx << 4);
        bsrc[i] = ((size_t)(nbx * 16 + (f >> 1)) * 32 + (f & 1)) * 32 + ln;
    }
    // A fragment bases for this warp's 2 mtiles
    u32 aF[2];
#pragma unroll
    for (int mt = 0; mt < 2; mt++)
        aF[mt] = sb + ((wg2 * 2 + mt) * 16 + (lane & 15)) * 80 + ((lane >> 4) * 16);

    auto issue = [&](int kk) {
        const u32 soff = (u32)(kk & 3) * XP_ST;
        if (doA) {
#pragma unroll
            for (int i = 0; i < 4; i++)
                cpa16(adst[i] + soff, asrc[i] + kk * 32);
        } else {
#pragma unroll
            for (int i = 0; i < 4; i++)
                cpa16(bdst[i] + soff, g_wih0p + bsrc[i] + (size_t)kk * 64);
        }
    };

    issue(0); cpa_commit();
    issue(1); cpa_commit();

#pragma unroll 1
    for (int kk = 0; kk < 16; kk += 2) {
        cpa_wait<0>();
        __syncthreads();
        if (kk + 2 < 16) {
            issue(kk + 2); cpa_commit();
            issue(kk + 3); cpa_commit();
        }
#pragma unroll
        for (int half = 0; half < 2; half++) {
            const int s = (kk + half) & 3;
            const uint4* bst = (const uint4*)(smem + (size_t)s * XP_ST + XP_B);
#pragma unroll
            for (int sub = 0; sub < 2; sub++) {
                u32 ah[2][4], al[2][4];
#pragma unroll
                for (int mt = 0; mt < 2; mt++) {
                    ldm4(ah[mt], aF[mt] + (u32)s * XP_ST + sub * 32);
                    ldm4(al[mt], aF[mt] + (u32)s * XP_ST + 10240 + sub * 32);
                }
#pragma unroll
                for (int j = 0; j < 4; j++) {
                    int f = (nq * 4 + j) * 2 + sub;
                    uint4 bp = bst[f * 32 + lane];
                    u32 bh[2] = {bp.x, bp.y}, bl[2] = {bp.z, bp.w};
#pragma unroll
                    for (int mt = 0; mt < 2; mt++) {
                        mma_f16(acc[mt][j], ah[mt], bh);
                        mma_f16(acc[mt][j], al[mt], bh);
                        mma_f16(acc[mt][j], ah[mt], bl);
                    }
                }
            }
        }
    }

    // epilogue
#pragma unroll
    for (int mt = 0; mt < 2; mt++) {
        int rl = (wg2 * 2 + mt) * 16 + qr;
        size_t rowbase = ((size_t)mb * 128 + rl) * G4;
#pragma unroll
        for (int j = 0; j < 4; j++) {
            int col = nbx * 128 + (nq * 4 + j) * 8 + qc * 2;
            float bv0 = bih0[col] + bhh0[col];
            float bv1 = bih0[col + 1] + bhh0[col + 1];
            *(float2*)&g_xproj[rowbase + col] =
                make_float2(acc[mt][j][0] + bv0, acc[mt][j][1] + bv1);
            *(float2*)&g_xproj[rowbase + (size_t)8 * G4 + col] =
                make_float2(acc[mt][j][2] + bv0, acc[mt][j][3] + bv1);
        }
    }
}

// ===========================================================================
// Persistent fused-step kernel (round-10 proven structure + B prefetch).
// Grid 128, 768 threads = 24 warps; wg = w&7 -> mtile, job = w>>3:
//   job0: h0(t+1)@Wih1 -> L1 part a; job1: h1(t)@Whh1 -> L1 part b (smem);
//   job2: h0(t+1)@Whh0 -> L0(t+1).
// B-staging threads prefetch next step's first 2 weight chunks before the
// grid barrier (weights step-invariant; per-thread cp.async groups).
// ===========================================================================
__global__ void __launch_bounds__(768) step_persist(
    const float* __restrict__ bih1, const float* __restrict__ bhh1)
{
    extern __shared__ char smem[];
    const int tid = threadIdx.x, bx = blockIdx.x;
    const int w = tid >> 5, lane = tid & 31, qr = lane >> 2, qc = lane & 3;
    const int wg = w & 7, job = w >> 3;
    const u32 sb = smem_u32(smem);
    const int n0 = bx * 8 + qc * 2;

    // ---- prologue: L0 step 0 (h0 = 0) on this CTA's 8 columns ----
    for (int i = tid; i < 128 * 8; i += 768) {
        int m = i >> 3, u = i & 7;
        int n = bx * 8 + u;
        const float* xr = g_xproj + (size_t)m * G4;
        float iv = xr[n], gv = xr[2048 + n], ov = xr[3072 + n];
        float cn = sigm(iv) * tanhf(gv);
        g_c0[m * HID + n] = cn;
        float h = sigm(ov) * tanhf(cn);
        __half hh = __float2half_rn(h);
        g_h0hi[1][m * HID + n] = hh;
        g_h0lo[1][m * HID + n] = __float2half_rn(h - __half2float(hh));
    }
    grid_barrier(0);

    // biases (L1) in regs (job0 uses them)
    float bs[4][2];
#pragma unroll
    for (int g = 0; g < 4; g++) {
        bs[g][0] = bih1[g * 1024 + n0] + bhh1[g * 1024 + n0];
        bs[g][1] = bih1[g * 1024 + n0 + 1] + bhh1[g * 1024 + n0 + 1];
    }
    // c-state in regs: job0 -> c1 (zeros), job2 -> c0 (from prologue)
    float cr[4] = {0.f, 0.f, 0.f, 0.f};
    if (job == 2) {
#pragma unroll
        for (int rr = 0; rr < 2; rr++) {
            int m = wg * 16 + qr + rr * 8;
            cr[rr * 2 + 0] = g_c0[m * HID + n0];
            cr[rr * 2 + 1] = g_c0[m * HID + n0 + 1];
        }
    }

    // ---- invariant staging coords ----
    const bool doA = (tid < 512);
    u32 adst[4]; u32 arow[4]; int aplane[4]; int aseg[4];
#pragma unroll
    for (int i = 0; i < 4; i++) {
        int idx = (tid & 511) + i * 512;
        aplane[i] = idx >> 9;
        arow[i] = (idx >> 2) & 127;
        aseg[i] = idx & 3;
        adst[i] = sb + aplane[i] * 10240 + arow[i] * 80 + aseg[i] * 16;
    }
    const int btl = tid & 255;
    const int tw = btl >> 5;
    const u32 bdst0 = sb + ST_B + (btl << 4);
    const size_t bsrc0 = (((size_t)((tw >> 1) * 128 + bx)) * 64 + (tw & 1)) * 32 + lane;
    const u32 jobAoff = (job == 1) ? 20480u : 0u;
    const u32 aF = sb + jobAoff + (wg * 16 + (lane & 15)) * 80 + ((lane >> 4) * 16);
    const int bmat = job * 256;

    float* red = (float*)smem;   // 16KB partial buffer (reuses stage 0 A area)

    // step-invariant B loader
    auto issueB = [&](int kk) {
        const u32 soff = (u32)(kk & 3) * ST_SZ;
        cpa16(bdst0 + soff,        g_wih1p + bsrc0 + (size_t)kk * 64);
        cpa16(bdst0 + soff + 4096, g_whh1p + bsrc0 + (size_t)kk * 64);
        cpa16(bdst0 + soff + 8192, g_whh0p + bsrc0 + (size_t)kk * 64);
    };

    // initial B prefetch (chunks 0,1)
    if (!doA) {
        issueB(0); cpa_commit();
        issueB(1); cpa_commit();
    }

#pragma unroll 1
    for (int t = 0; t < STEPS; t++) {
        const int do_l0 = (t < STEPS - 1);
        const __half* Ap0 = g_h0hi[(t + 1) & 1];
        const __half* Ap1 = g_h0lo[(t + 1) & 1];
        const __half* Ap2 = g_h1hi[t & 1];
        const __half* Ap3 = g_h1lo[t & 1];

        float acc[4][4];
#pragma unroll
        for (int j = 0; j < 4; j++)
#pragma unroll
            for (int k = 0; k < 4; k++) acc[j][k] = 0.f;

        auto issueA = [&](int kk) {
            const u32 soff = (u32)(kk & 3) * ST_SZ;
#pragma unroll
            for (int i = 0; i < 4; i++) {
                const __half* base = (aplane[i] == 0) ? Ap0 :
                                     (aplane[i] == 1) ? Ap1 :
                                     (aplane[i] == 2) ? Ap2 : Ap3;
                cpa16(adst[i] + soff,
                      base + (size_t)arow[i] * HID + kk * 32 + aseg[i] * 8);
            }
        };

        if (doA) {
            issueA(0); cpa_commit();
            issueA(1); cpa_commit();
        }

#pragma unroll 1
        for (int kk = 0; kk < 32; kk += 2) {
            cpa_wait<0>();
            __syncthreads();
            if (kk + 2 < 32) {
                if (doA) issueA(kk + 2); else issueB(kk + 2);
                cpa_commit();
                if (doA) issueA(kk + 3); else issueB(kk + 3);
                cpa_commit();
            }
#pragma unroll
            for (int half = 0; half < 2; half++) {
                const int s = (kk + half) & 3;
                const u32 aBase = aF + (u32)s * ST_SZ;
                const uint4* bst = (const uint4*)(smem + (size_t)s * ST_SZ + ST_B);
#pragma unroll
                for (int sub = 0; sub < 2; sub++) {
                    u32 ah[4], al[4];
                    ldm4(ah, aBase + sub * 32);
                    ldm4(al, aBase + sub * 32 + 10240);
#pragma unroll
                    for (int nt = 0; nt < 4; nt++) {
                        uint4 bp = bst[bmat + (nt * 2 + sub) * 32 + lane];
                        u32 bh[2] = {bp.x, bp.y}, bl[2] = {bp.z, bp.w};
                        mma_f16(acc[nt], ah, bh);
                        mma_f16(acc[nt], al, bh);
                        mma_f16(acc[nt], ah, bl);
                    }
                }
            }
        }
        cpa_wait<0>();
        __syncthreads();

        // prefetch next step's B (weights step-invariant; stages 0,1 free)
        if (!doA && t + 1 < STEPS) {
            issueB(0); cpa_commit();
            issueB(1); cpa_commit();
        }

        // ---- combine: job1 publishes L1 partials ----
        if (job == 1) {
#pragma unroll
            for (int nt = 0; nt < 4; nt++)
#pragma unroll
                for (int r = 0; r < 4; r++)
                    red[(((wg * 4 + nt) * 4 + r) << 5) + lane] = acc[nt][r];
        }
        __syncthreads();

        if (job == 0) {
            // ---- L1(t) epilogue ----
            __half* Hhi = g_h1hi[(t + 1) & 1];
            __half* Hlo = g_h1lo[(t + 1) & 1];
#pragma unroll
            for (int rr = 0; rr < 2; rr++) {
                int m = wg * 16 + qr + rr * 8;
                __half hh[2], hl[2];
#pragma unroll
                for (int e = 0; e < 2; e++) {
                    int ri = rr * 2 + e;
                    float pI = red[(((wg * 4 + 0) * 4 + ri) << 5) + lane];
                    float pF = red[(((wg * 4 + 1) * 4 + ri) << 5) + lane];
                    float pG = red[(((wg * 4 + 2) * 4 + ri) << 5) + lane];
                    float pO = red[(((wg * 4 + 3) * 4 + ri) << 5) + lane];
                    float iv = acc[0][ri] + pI + bs[0][e];
                    float fv = acc[1][ri] + pF + bs[1][e];
                    float gv = acc[2][ri] + pG + bs[2][e];
                    float ov = acc[3][ri] + pO + bs[3][e];
                    float cn = sigm(fv) * cr[ri] + sigm(iv) * tanhf(gv);
                    cr[ri] = cn;
                    float h = sigm(ov) * tanhf(cn);
                    hh[e] = __float2half_rn(h);
                    hl[e] = __float2half_rn(h - __half2float(hh[e]));
                }
                *(__half2*)&Hhi[m * HID + n0] = __halves2half2(hh[0], hh[1]);
                *(__half2*)&Hlo[m * HID + n0] = __halves2half2(hl[0], hl[1]);
            }
        } else if (job == 2 && do_l0) {
            // ---- L0(t+1) epilogue ----
            const float* xp = g_xproj + (size_t)(t + 1) * BATCH * G4;
            __half* Hhi = g_h0hi[t & 1];
            __half* Hlo = g_h0lo[t & 1];
#pragma unroll
            for (int rr = 0; rr < 2; rr++) {
                int m = wg * 16 + qr + rr * 8;
                const float* xr = xp + (size_t)m * G4 + n0;
                float2 xi = *(const float2*)(xr);
                float2 xf = *(const float2*)(xr + 1024);
                float2 xg = *(const float2*)(xr + 2048);
                float2 xo = *(const float2*)(xr + 3072);
                __half hh[2], hl[2];
#pragma unroll
                for (int e = 0; e < 2; e++) {
                    int ri = rr * 2 + e;
                    float iv = acc[0][ri] + (e ? xi.y : xi.x);
                    float fv = acc[1][ri] + (e ? xf.y : xf.x);
                    float gv = acc[2][ri] + (e ? xg.y : xg.x);
                    float ov = acc[3][ri] + (e ? xo.y : xo.x);
                    float cn = sigm(fv) * cr[ri] + sigm(iv) * tanhf(gv);
                    cr[ri] = cn;
                    float h = sigm(ov) * tanhf(cn);
                    hh[e] = __float2half_rn(h);
                    hl[e] = __float2half_rn(h - __half2float(hh[e]));
                }
                *(__half2*)&Hhi[m * HID + n0] = __halves2half2(hh[0], hh[1]);
                *(__half2*)&Hlo[m * HID + n0] = __halves2half2(hl[0], hl[1]);
            }
        }
        grid_barrier(t + 1);
    }
}

// ---------------- classifier (unchanged) ------------------------------------
__global__ void __launch_bounds__(256) classifier_kernel(
    const float* __restrict__ Wcls, const float* __restrict__ bcls,
    const float* __restrict__ dropu, float* __restrict__ out)
{
    int gw = (blockIdx.x * blockDim.x + threadIdx.x) >> 5;
    int lane = threadIdx.x & 31;
    int j = gw >> 5;
    int b0 = (gw & 31) * 4;
    const __half* hi = g_h1hi[0];
    const __half* lo = g_h1lo[0];

    float acc[4] = {0.f, 0.f, 0.f, 0.f};
#pragma unroll
    for (int it = 0; it < 8; ++it) {
        int h = it * 128 + lane * 4;
        float4 wv = *(const float4*)&Wcls[(size_t)j * HID + h];
#pragma unroll
        for (int bi = 0; bi < 4; ++bi) {
            int b = b0 + bi;
            int idx = b * HID + h;
            __half2 a0 = *(const __half2*)&hi[idx];
            __half2 a1 = *(const __half2*)&hi[idx + 2];
            __half2 c0 = *(const __half2*)&lo[idx];
            __half2 c1 = *(const __half2*)&lo[idx + 2];
            float2 f0 = __half22float2(a0), f1 = __half22float2(a1);
            float2 g0 = __half22float2(c0), g1 = __half22float2(c1);
            float x0 = f0.x + g0.x, x1 = f0.y + g0.y;
            float x2 = f1.x + g1.x, x3 = f1.y + g1.y;
            float4 u = *(const float4*)&dropu[(size_t)b * HID + h];
            acc[bi] += (u.x > 0.5f ? x0 : 0.f) * wv.x
                     + (u.y > 0.5f ? x1 : 0.f) * wv.y
                     + (u.z > 0.5f ? x2 : 0.f) * wv.z
                     + (u.w > 0.5f ? x3 : 0.f) * wv.w;
        }
    }
#pragma unroll
    for (int bi = 0; bi < 4; ++bi) {
        float v = acc[bi];
#pragma unroll
        for (int off = 16; off; off >>= 1)
            v += __shfl_xor_sync(0xffffffffu, v, off);
        if (lane == 0)
            out[(size_t)(b0 + bi) * 1000 + j] = 2.0f * v + bcls[j];
    }
}

// ---------------- launch ----------------------------------------------------
extern "C" void kernel_launch(void* const* d_in, const int* in_sizes, int n_in,
                              void* d_out, int out_size)
{
    const float* xs    = (const float*)d_in[0];
    const float* Wih0  = (const float*)d_in[1];
    const float* Whh0  = (const float*)d_in[2];
    const float* bih0  = (const float*)d_in[3];
    const float* bhh0  = (const float*)d_in[4];
    const float* Wih1  = (const float*)d_in[5];
    const float* Whh1  = (const float*)d_in[6];
    const float* bih1  = (const float*)d_in[7];
    const float* bhh1  = (const float*)d_in[8];
    const float* Wcls  = (const float*)d_in[9];
    const float* bcls  = (const float*)d_in[10];
    const float* dropu = (const float*)d_in[11];
    float* out = (float*)d_out;

    cudaFuncSetAttribute(step_persist, cudaFuncAttributeMaxDynamicSharedMemorySize, PS_TOTAL);
    cudaFuncSetAttribute(xproj_kernel, cudaFuncAttributeMaxDynamicSharedMemorySize, XP_TOTAL);

    init_states<<<(BATCH * HID + 255) / 256, 256>>>();
    pack_all<<<(PACK_TOTAL + 255) / 256, 256>>>(Whh0, Wih1, Whh1, Wih0, xs);
    xproj_kernel<<<dim3(32, 64), 512, XP_TOTAL>>>(bih0, bhh0);
    step_persist<<<128, 768, PS_TOTAL>>>(bih1, bhh1);
    classifier_kernel<<<4000, 256>>>(Wcls, bcls, dropu, out);
}